// round 1
// baseline (speedup 1.0000x reference)
#include <cuda_runtime.h>

// LowRankBilinearFusion: out[b,m,n,f] = relu( sum_k Wp[f,k] * (u[b,m]·Wu[k]) * (v[b,n]·Wv[k]) + bp[f] )
//
// Decomposition:
//   K1: up[bm,k] = u[bm,:] · Wu[k,:]          (1024 x 256, K=1024)
//   K2: vp[bn,k] = v[bn,:] · Wv[k,:]          (4096 x 256, K=2048)
//   K3: per (b,m): O = (vp[b] * diag(up[b,m])) @ Wp^T + bp, relu   (128 x 256, K=256) x 1024

namespace {

constexpr int Bsz = 32;
constexpr int Mq  = 32;
constexpr int Rr  = 128;
constexpr int DL  = 1024;   // d_lang
constexpr int DR  = 2048;   // d_region
constexpr int DK  = 256;    // d_rank
constexpr int DF  = 256;    // d_fusion

// GEMM tile config: C[BM x BN] per block, K-step BK, 256 threads, 4x4 micro-tile.
constexpr int BM = 64;
constexpr int BN = 64;
constexpr int BK = 16;
constexpr int SLD = BM + 4;   // 68: padded smem row stride, keeps float4 (16B) alignment

// Scratch (allocation-guard safe: __device__ globals)
__device__ float g_up[Bsz * Mq * DK];    // 1 MB
__device__ float g_vp[Bsz * Rr * DK];    // 4 MB

// Generic C = A @ B^T tile body. A: [rows x K] row-major, Bm: [N x K] row-major,
// C: [rows x N] row-major. blockIdx.x -> n-tile, blockIdx.y -> m-tile.
// All dims assumed divisible by tile sizes (true for this problem).
__device__ __forceinline__ void gemm_abt_body(
    const float* __restrict__ A, const float* __restrict__ Bm,
    float* __restrict__ C, int K, int N)
{
    __shared__ float As[BK * SLD];
    __shared__ float Bs[BK * SLD];

    const int tid = threadIdx.x;
    const int tx = tid & 15;        // 0..15 -> n
    const int ty = tid >> 4;        // 0..15 -> m
    const int m0 = blockIdx.y * BM;
    const int n0 = blockIdx.x * BN;

    const int lr = tid >> 2;        // 0..63: row within tile for loading
    const int kv = tid & 3;         // 0..3 : which float4 of the BK=16 k-slice

    float c[4][4] = {};

    for (int kt = 0; kt < K; kt += BK) {
        const float4 av = *(const float4*)&A[(size_t)(m0 + lr) * K + kt + kv * 4];
        const float4 bv = *(const float4*)&Bm[(size_t)(n0 + lr) * K + kt + kv * 4];
        As[(kv * 4 + 0) * SLD + lr] = av.x;
        As[(kv * 4 + 1) * SLD + lr] = av.y;
        As[(kv * 4 + 2) * SLD + lr] = av.z;
        As[(kv * 4 + 3) * SLD + lr] = av.w;
        Bs[(kv * 4 + 0) * SLD + lr] = bv.x;
        Bs[(kv * 4 + 1) * SLD + lr] = bv.y;
        Bs[(kv * 4 + 2) * SLD + lr] = bv.z;
        Bs[(kv * 4 + 3) * SLD + lr] = bv.w;
        __syncthreads();

        #pragma unroll
        for (int kk = 0; kk < BK; kk++) {
            const float4 a = *(const float4*)&As[kk * SLD + ty * 4];
            const float4 b = *(const float4*)&Bs[kk * SLD + tx * 4];
            c[0][0] += a.x * b.x; c[0][1] += a.x * b.y; c[0][2] += a.x * b.z; c[0][3] += a.x * b.w;
            c[1][0] += a.y * b.x; c[1][1] += a.y * b.y; c[1][2] += a.y * b.z; c[1][3] += a.y * b.w;
            c[2][0] += a.z * b.x; c[2][1] += a.z * b.y; c[2][2] += a.z * b.z; c[2][3] += a.z * b.w;
            c[3][0] += a.w * b.x; c[3][1] += a.w * b.y; c[3][2] += a.w * b.z; c[3][3] += a.w * b.w;
        }
        __syncthreads();
    }

    #pragma unroll
    for (int i = 0; i < 4; i++) {
        float4 v = make_float4(c[i][0], c[i][1], c[i][2], c[i][3]);
        *(float4*)&C[(size_t)(m0 + ty * 4 + i) * N + n0 + tx * 4] = v;
    }
}

__global__ __launch_bounds__(256) void up_kernel(
    const float* __restrict__ u, const float* __restrict__ Wu)
{
    gemm_abt_body(u, Wu, g_up, DL, DK);
}

__global__ __launch_bounds__(256) void vp_kernel(
    const float* __restrict__ v, const float* __restrict__ Wv)
{
    gemm_abt_body(v, Wv, g_vp, DR, DK);
}

// Fused bilinear + projection + bias + relu.
// blockIdx.y = bm (0..1023), blockIdx.x = nt + 2*ft  (nt in {0,1}, ft in {0..3}).
// Computes O[n0:n0+64, f0:f0+64] for pair (b,m) where
//   O = (vp[b] * diag(up[b,m])) @ Wp^T + bp, relu.
__global__ __launch_bounds__(256) void fusion_kernel(
    const float* __restrict__ Wp, const float* __restrict__ bp,
    float* __restrict__ out)
{
    __shared__ float As[BK * SLD];
    __shared__ float Bs[BK * SLD];
    __shared__ float ws[DK];
    __shared__ float bs[BN];

    const int tid = threadIdx.x;
    const int tx = tid & 15;
    const int ty = tid >> 4;

    const int bm = blockIdx.y;          // 0..1023
    const int b  = bm >> 5;             // 0..31
    const int nt = blockIdx.x & 1;      // 0..1
    const int ft = blockIdx.x >> 1;     // 0..3
    const int n0 = nt * BM;
    const int f0 = ft * BN;

    const float* __restrict__ A = g_vp + (size_t)b * Rr * DK;   // vp[b]: 128 x 256
    const float* __restrict__ w = g_up + (size_t)bm * DK;       // up[b,m]: 256

    ws[tid] = w[tid];                   // DK == 256 == blockDim
    if (tid < BN) bs[tid] = bp[f0 + tid];
    __syncthreads();

    const int lr = tid >> 2;
    const int kv = tid & 3;

    float c[4][4] = {};

    for (int kt = 0; kt < DK; kt += BK) {
        float4 av = *(const float4*)&A[(size_t)(n0 + lr) * DK + kt + kv * 4];
        const float4 bv = *(const float4*)&Wp[(size_t)(f0 + lr) * DK + kt + kv * 4];
        // scale A tile by up[b,m,k]
        av.x *= ws[kt + kv * 4 + 0];
        av.y *= ws[kt + kv * 4 + 1];
        av.z *= ws[kt + kv * 4 + 2];
        av.w *= ws[kt + kv * 4 + 3];
        As[(kv * 4 + 0) * SLD + lr] = av.x;
        As[(kv * 4 + 1) * SLD + lr] = av.y;
        As[(kv * 4 + 2) * SLD + lr] = av.z;
        As[(kv * 4 + 3) * SLD + lr] = av.w;
        Bs[(kv * 4 + 0) * SLD + lr] = bv.x;
        Bs[(kv * 4 + 1) * SLD + lr] = bv.y;
        Bs[(kv * 4 + 2) * SLD + lr] = bv.z;
        Bs[(kv * 4 + 3) * SLD + lr] = bv.w;
        __syncthreads();

        #pragma unroll
        for (int kk = 0; kk < BK; kk++) {
            const float4 a = *(const float4*)&As[kk * SLD + ty * 4];
            const float4 b2 = *(const float4*)&Bs[kk * SLD + tx * 4];
            c[0][0] += a.x * b2.x; c[0][1] += a.x * b2.y; c[0][2] += a.x * b2.z; c[0][3] += a.x * b2.w;
            c[1][0] += a.y * b2.x; c[1][1] += a.y * b2.y; c[1][2] += a.y * b2.z; c[1][3] += a.y * b2.w;
            c[2][0] += a.z * b2.x; c[2][1] += a.z * b2.y; c[2][2] += a.z * b2.z; c[2][3] += a.z * b2.w;
            c[3][0] += a.w * b2.x; c[3][1] += a.w * b2.y; c[3][2] += a.w * b2.z; c[3][3] += a.w * b2.w;
        }
        __syncthreads();
    }

    // epilogue: bias + relu, write out[b,m,n,f]
    float* __restrict__ Ob = out + (size_t)bm * Rr * DF;
    #pragma unroll
    for (int i = 0; i < 4; i++) {
        float4 v;
        v.x = fmaxf(c[i][0] + bs[tx * 4 + 0], 0.0f);
        v.y = fmaxf(c[i][1] + bs[tx * 4 + 1], 0.0f);
        v.z = fmaxf(c[i][2] + bs[tx * 4 + 2], 0.0f);
        v.w = fmaxf(c[i][3] + bs[tx * 4 + 3], 0.0f);
        *(float4*)&Ob[(size_t)(n0 + ty * 4 + i) * DF + f0 + tx * 4] = v;
    }
}

} // namespace

extern "C" void kernel_launch(void* const* d_in, const int* in_sizes, int n_in,
                              void* d_out, int out_size)
{
    (void)in_sizes; (void)n_in; (void)out_size;
    const float* u  = (const float*)d_in[0];   // (32, 32, 1024)
    const float* v  = (const float*)d_in[1];   // (32, 128, 2048)
    const float* Wu = (const float*)d_in[2];   // (256, 1024)
    const float* Wv = (const float*)d_in[3];   // (256, 2048)
    const float* Wp = (const float*)d_in[4];   // (256, 256)
    const float* bp = (const float*)d_in[5];   // (256,)
    float* out = (float*)d_out;                // (32, 32, 128, 256)

    // K1: up = u @ Wu^T   -> g_up (1024 x 256)
    up_kernel<<<dim3(DK / BN, (Bsz * Mq) / BM), 256>>>(u, Wu);
    // K2: vp = v @ Wv^T   -> g_vp (4096 x 256)
    vp_kernel<<<dim3(DK / BN, (Bsz * Rr) / BM), 256>>>(v, Wv);
    // K3: fused bilinear + projection + bias + relu
    fusion_kernel<<<dim3((Rr / BM) * (DF / BN), Bsz * Mq), 256>>>(Wp, bp, out);
}

// round 5
// speedup vs baseline: 1.3980x; 1.3980x over previous
#include <cuda_runtime.h>
#include <cuda_fp16.h>
#include <cstdint>

// LowRankBilinearFusion via fp16x3 split mma.sync (sm_80+ PTX, no "a"-features).
// Each fp32 GEMM C = A @ B^T is computed as:
//   A = Ah + Al, B = Bh + Bl (fp16 hi/lo split); C += Ah*Bh + Ah*Bl + Al*Bh (fp32 accum)
// leaving only the ~2^-22 lo*lo term -> near-fp32 precision.
//   K1: up[1024,256] = u[1024,1024] @ Wu^T
//   K2: vp[4096,256] = v[4096,2048] @ Wv^T
//   K3: per bm: out[bm] = relu( (vp[b]*diag(up[bm])) @ Wp^T + bp )  (128x256, K=256)

namespace {

constexpr int Bsz = 32, Mq = 32, Rr = 128;
constexpr int DL = 1024, DR = 2048, DK = 256, DF = 256;
constexpr int BK = 32;   // K per stage chunk (2 x k16)

// smem layout in 32-bit words:
//   ws[256] | bs[128] | stage0{AH,AL,BH,BL}[4*2048] | stage1{...}[4*2048]
constexpr int OFF_WS  = 0;
constexpr int OFF_BS  = 256;
constexpr int OFF_BUF = 384;
constexpr int CH      = 2048;        // words per sub-buffer (8 KB)
constexpr int STAGE   = 4 * CH;      // 8192 words (32 KB)
constexpr int SMEM_WORDS = OFF_BUF + 2 * STAGE;
constexpr int SMEM_BYTES = SMEM_WORDS * 4;   // 67072

__device__ float g_up[Bsz * Mq * DK];   // 1 MB
__device__ float g_vp[Bsz * Rr * DK];   // 4 MB

__device__ __forceinline__ void mma_fp16(float* c, const uint32_t* a, const uint32_t* b) {
    asm volatile(
        "mma.sync.aligned.m16n8k16.row.col.f32.f16.f16.f32 "
        "{%0,%1,%2,%3}, {%4,%5,%6,%7}, {%8,%9}, {%0,%1,%2,%3};"
        : "+f"(c[0]), "+f"(c[1]), "+f"(c[2]), "+f"(c[3])
        : "r"(a[0]), "r"(a[1]), "r"(a[2]), "r"(a[3]), "r"(b[0]), "r"(b[1]));
}

__device__ __forceinline__ void split2(float x, __half& hi, __half& lo) {
    hi = __float2half_rn(x);
    lo = __float2half_rn(x - __half2float(hi));
}

__device__ __forceinline__ uint32_t pack2(__half a, __half b) {
    return (uint32_t)__half_as_ushort(a) | ((uint32_t)__half_as_ushort(b) << 16);
}

// ---- global loads: each thread grabs 4 A-float4 and 4 B-float4 per chunk ----
template <int KDIM, bool SCALE>
__device__ __forceinline__ void ldg_chunk(
    const float* __restrict__ A, const float* __restrict__ Bw,
    const float* __restrict__ ws, int kt, int tid, float4* ar, float4* br)
{
    #pragma unroll
    for (int j = 0; j < 4; j++) {
        const int i = tid + 256 * j;     // 0..1023 float4 slots
        const int row = i >> 3;          // 0..127
        const int c4  = i & 7;           // which float4 of the 32-k chunk
        float4 va = *(const float4*)(A + (size_t)row * KDIM + kt + c4 * 4);
        if (SCALE) {
            const float4 w4 = *(const float4*)&ws[kt + c4 * 4];
            va.x *= w4.x; va.y *= w4.y; va.z *= w4.z; va.w *= w4.w;
        }
        ar[j] = va;
        br[j] = *(const float4*)(Bw + (size_t)row * KDIM + kt + c4 * 4);
    }
}

// ---- fragment-permuted smem stores with fp16 hi/lo split ----
// m16n8k16 A frag (g=lane>>2, t=lane&3): a0=(g,2t:2t+1) a1=(g+8,..) a2=(g,2t+8:2t+9) a3=(g+8,..)
// B frag: b0=(2t:2t+1, n=g), b1=(2t+8:2t+9, n=g)
__device__ __forceinline__ void sts_chunk(
    uint32_t* __restrict__ AH, uint32_t* __restrict__ AL,
    uint32_t* __restrict__ BH, uint32_t* __restrict__ BL,
    int tid, const float4* ar, const float4* br)
{
    #pragma unroll
    for (int j = 0; j < 4; j++) {
        const int i = tid + 256 * j;
        const int row = i >> 3;
        const int c4  = i & 7;
        const int kc   = c4 >> 2;        // which k16 sub-chunk
        const int reg  = (c4 >> 1) & 1;  // kk>>3 within k16
        const int lp   = (c4 & 1) * 2;   // lane pair base (t = kk>>1 & 3)
        // A
        {
            const int mt = row >> 4, r = row & 15, half = r >> 3, g = r & 7;
            const int a0 = ((kc * 8 + mt) * 32 + g * 4 + lp) * 4 + half + 2 * reg;
            __half h0,l0,h1,l1,h2,l2,h3,l3;
            split2(ar[j].x,h0,l0); split2(ar[j].y,h1,l1);
            split2(ar[j].z,h2,l2); split2(ar[j].w,h3,l3);
            AH[a0]     = pack2(h0, h1);  AH[a0 + 4] = pack2(h2, h3);
            AL[a0]     = pack2(l0, l1);  AL[a0 + 4] = pack2(l2, l3);
        }
        // B
        {
            const int nt = row >> 3, g = row & 7;
            const int b0 = ((kc * 16 + nt) * 32 + g * 4 + lp) * 2 + reg;
            __half h0,l0,h1,l1,h2,l2,h3,l3;
            split2(br[j].x,h0,l0); split2(br[j].y,h1,l1);
            split2(br[j].z,h2,l2); split2(br[j].w,h3,l3);
            BH[b0]     = pack2(h0, h1);  BH[b0 + 2] = pack2(h2, h3);
            BL[b0]     = pack2(l0, l1);  BL[b0 + 2] = pack2(l2, l3);
        }
    }
}

__device__ __forceinline__ void compute_chunk(
    const uint32_t* __restrict__ AH, const uint32_t* __restrict__ AL,
    const uint32_t* __restrict__ BH, const uint32_t* __restrict__ BL,
    int wm, int wn, int lane, float c[2][8][4])
{
    #pragma unroll
    for (int kc = 0; kc < 2; kc++) {
        uint32_t ah[2][4], al[2][4];
        #pragma unroll
        for (int mt2 = 0; mt2 < 2; mt2++) {
            const int base = ((kc * 8 + wm * 2 + mt2) * 32 + lane) * 4;
            const uint4 vh = *(const uint4*)(AH + base);
            ah[mt2][0] = vh.x; ah[mt2][1] = vh.y; ah[mt2][2] = vh.z; ah[mt2][3] = vh.w;
            const uint4 vl = *(const uint4*)(AL + base);
            al[mt2][0] = vl.x; al[mt2][1] = vl.y; al[mt2][2] = vl.z; al[mt2][3] = vl.w;
        }
        uint32_t bh[8][2], bl[8][2];
        #pragma unroll
        for (int j = 0; j < 8; j++) {
            const int base = ((kc * 16 + wn * 8 + j) * 32 + lane) * 2;
            const uint2 vh = *(const uint2*)(BH + base);
            bh[j][0] = vh.x; bh[j][1] = vh.y;
            const uint2 vl = *(const uint2*)(BL + base);
            bl[j][0] = vl.x; bl[j][1] = vl.y;
        }
        #pragma unroll
        for (int mt2 = 0; mt2 < 2; mt2++)
            #pragma unroll
            for (int j = 0; j < 8; j++) {
                mma_fp16(c[mt2][j], ah[mt2], bh[j]);   // hi*hi
                mma_fp16(c[mt2][j], al[mt2], bh[j]);   // lo*hi
                mma_fp16(c[mt2][j], ah[mt2], bl[j]);   // hi*lo
            }
    }
}

// C[128 x 128-tile] = A[128 x KDIM] @ B(rows n0..n0+127)[x KDIM]^T.
// A, C pre-offset to CTA m rows; B pre-offset to n0; C row stride 256.
template <int KDIM, bool SCALE, bool RELU>
__device__ __forceinline__ void gemm_body(
    const float* __restrict__ A, const float* __restrict__ Bw,
    const float* __restrict__ wvec, const float* __restrict__ bias,
    float* __restrict__ C, int n0)
{
    extern __shared__ uint32_t smem[];
    constexpr int NC = KDIM / BK;

    const int tid = threadIdx.x;
    const int wid = tid >> 5;
    const int lane = tid & 31;
    const int wm = wid & 3;     // warp m (0..3)
    const int wn = wid >> 2;    // warp n (0..1)

    float* ws = (float*)(smem + OFF_WS);
    float* bs = (float*)(smem + OFF_BS);
    uint32_t* buf[2] = { smem + OFF_BUF, smem + OFF_BUF + STAGE };

    if (SCALE) ws[tid] = wvec[tid];
    if (RELU && tid < 128) bs[tid] = bias[n0 + tid];
    __syncthreads();   // ws/bs visible before any use (fixes R4 race)

    float c[2][8][4] = {};
    float4 ar[4], br[4];

    ldg_chunk<KDIM, SCALE>(A, Bw, ws, 0, tid, ar, br);
    sts_chunk(buf[0], buf[0] + CH, buf[0] + 2 * CH, buf[0] + 3 * CH, tid, ar, br);
    __syncthreads();

    for (int ck = 0; ck < NC; ck++) {
        const int par = ck & 1;
        if (ck + 1 < NC)
            ldg_chunk<KDIM, SCALE>(A, Bw, ws, (ck + 1) * BK, tid, ar, br);
        uint32_t* b = buf[par];
        compute_chunk(b, b + CH, b + 2 * CH, b + 3 * CH, wm, wn, lane, c);
        __syncthreads();
        if (ck + 1 < NC) {
            uint32_t* nb = buf[par ^ 1];
            sts_chunk(nb, nb + CH, nb + 2 * CH, nb + 3 * CH, tid, ar, br);
            __syncthreads();
        }
    }

    // epilogue: c frag (g,2t),(g,2t+1),(g+8,2t),(g+8,2t+1)
    const int g = lane >> 2, t = lane & 3;
    #pragma unroll
    for (int mt2 = 0; mt2 < 2; mt2++) {
        const int row0 = wm * 32 + mt2 * 16 + g;
        #pragma unroll
        for (int j = 0; j < 8; j++) {
            const int col_l = wn * 64 + j * 8 + t * 2;
            float2 v0 = make_float2(c[mt2][j][0], c[mt2][j][1]);
            float2 v1 = make_float2(c[mt2][j][2], c[mt2][j][3]);
            if (RELU) {
                const float b0 = bs[col_l], b1 = bs[col_l + 1];
                v0.x = fmaxf(v0.x + b0, 0.0f); v0.y = fmaxf(v0.y + b1, 0.0f);
                v1.x = fmaxf(v1.x + b0, 0.0f); v1.y = fmaxf(v1.y + b1, 0.0f);
            }
            *(float2*)(C + (size_t)row0 * 256 + n0 + col_l)       = v0;
            *(float2*)(C + (size_t)(row0 + 8) * 256 + n0 + col_l) = v1;
        }
    }
}

__global__ __launch_bounds__(256, 1) void k1_up(const float* __restrict__ u,
                                                const float* __restrict__ Wu) {
    const int n0 = blockIdx.x * 128;
    gemm_body<DL, false, false>(u + (size_t)blockIdx.y * 128 * DL, Wu + (size_t)n0 * DL,
                                nullptr, nullptr,
                                g_up + (size_t)blockIdx.y * 128 * DK, n0);
}

__global__ __launch_bounds__(256, 1) void k2_vp(const float* __restrict__ v,
                                                const float* __restrict__ Wv) {
    const int n0 = blockIdx.x * 128;
    gemm_body<DR, false, false>(v + (size_t)blockIdx.y * 128 * DR, Wv + (size_t)n0 * DR,
                                nullptr, nullptr,
                                g_vp + (size_t)blockIdx.y * 128 * DK, n0);
}

__global__ __launch_bounds__(256, 1) void k3_fuse(const float* __restrict__ Wp,
                                                  const float* __restrict__ bp,
                                                  float* __restrict__ out) {
    const int bm = blockIdx.y;
    const int b  = bm >> 5;
    const int n0 = blockIdx.x * 128;
    gemm_body<DK, true, true>(g_vp + (size_t)b * Rr * DK, Wp + (size_t)n0 * DK,
                              g_up + (size_t)bm * DK, bp,
                              out + (size_t)bm * Rr * DF, n0);
}

} // namespace

extern "C" void kernel_launch(void* const* d_in, const int* in_sizes, int n_in,
                              void* d_out, int out_size)
{
    (void)in_sizes; (void)n_in; (void)out_size;
    const float* u  = (const float*)d_in[0];   // (32, 32, 1024)
    const float* v  = (const float*)d_in[1];   // (32, 128, 2048)
    const float* Wu = (const float*)d_in[2];   // (256, 1024)
    const float* Wv = (const float*)d_in[3];   // (256, 2048)
    const float* Wp = (const float*)d_in[4];   // (256, 256)
    const float* bp = (const float*)d_in[5];   // (256,)
    float* out = (float*)d_out;                // (32, 32, 128, 256)

    static bool attr_set = false;
    if (!attr_set) {
        cudaFuncSetAttribute(k1_up,   cudaFuncAttributeMaxDynamicSharedMemorySize, SMEM_BYTES);
        cudaFuncSetAttribute(k2_vp,   cudaFuncAttributeMaxDynamicSharedMemorySize, SMEM_BYTES);
        cudaFuncSetAttribute(k3_fuse, cudaFuncAttributeMaxDynamicSharedMemorySize, SMEM_BYTES);
        attr_set = true;
    }

    k1_up<<<dim3(2, 8),     256, SMEM_BYTES>>>(u, Wu);         // 16 CTAs
    k2_vp<<<dim3(2, 32),    256, SMEM_BYTES>>>(v, Wv);         // 64 CTAs
    k3_fuse<<<dim3(2, 1024), 256, SMEM_BYTES>>>(Wp, bp, out);  // 2048 CTAs
}

// round 7
// speedup vs baseline: 2.1957x; 1.5706x over previous
#include <cuda_runtime.h>
#include <cuda_fp16.h>
#include <cstdint>

// LowRankBilinearFusion via fp16x3 split mma.sync with pre-permuted global
// fragment buffers. C = A@B^T as Ah*Bh + Al*Bh + Ah*Bl (fp32 accum).
//
// Canonical fragment-permuted layouts (match mma.m16n8k16.row.col):
//  A word idx: ((k16*(ROWS/16)+m16)*32+lane)*4+s, s in 0..3:
//    half2{ X[m16*16+(s&1)*8+g][k16*16+(s>>1)*8+2t], X[..+1] }, g=lane>>2, t=lane&3
//  B word idx: ((k16*(NROWS/8)+n8)*32+lane)*2+s, s in 0..1:
//    half2{ X[n8*8+g][k16*16+s*8+2t], X[..+1] }

namespace {

constexpr int Bsz = 32, Mq = 32, Rr = 128;
constexpr int DL = 1024, DR = 2048, DK = 256, DF = 256;

// ---- global scratch (referenced ONLY from device code; never passed from host) ----
__device__ float g_up[Bsz * Mq * DK];            // 1 MB fp32
__device__ float g_vp[Bsz * Rr * DK];            // 4 MB fp32
__device__ uint32_t uA_h[DL * Bsz * Mq / 2],  uA_l[DL * Bsz * Mq / 2];
__device__ uint32_t vA_h[(size_t)Bsz * Rr * DR / 2], vA_l[(size_t)Bsz * Rr * DR / 2];
__device__ uint32_t WuB_h[DK * DL / 2], WuB_l[DK * DL / 2];
__device__ uint32_t WvB_h[DK * DR / 2], WvB_l[DK * DR / 2];
__device__ uint32_t WpB_h[DF * DK / 2], WpB_l[DF * DK / 2];

__device__ __forceinline__ void mma_fp16(float* c, const uint32_t* a, const uint32_t* b) {
    asm volatile(
        "mma.sync.aligned.m16n8k16.row.col.f32.f16.f16.f32 "
        "{%0,%1,%2,%3}, {%4,%5,%6,%7}, {%8,%9}, {%0,%1,%2,%3};"
        : "+f"(c[0]), "+f"(c[1]), "+f"(c[2]), "+f"(c[3])
        : "r"(a[0]), "r"(a[1]), "r"(a[2]), "r"(a[3]), "r"(b[0]), "r"(b[1]));
}

__device__ __forceinline__ void split2(float x, __half& hi, __half& lo) {
    hi = __float2half_rn(x);
    lo = __float2half_rn(x - __half2float(hi));
}
__device__ __forceinline__ uint32_t pack2(__half a, __half b) {
    return (uint32_t)__half_as_ushort(a) | ((uint32_t)__half_as_ushort(b) << 16);
}
__device__ __forceinline__ void split_pack2(float x0, float x1, uint32_t& h, uint32_t& l) {
    __half h0, l0, h1, l1;
    split2(x0, h0, l0); split2(x1, h1, l1);
    h = pack2(h0, h1); l = pack2(l0, l1);
}

// ---- prep bodies: fp32 row-major -> permuted hi/lo fp16 frag buffers ----
__device__ __forceinline__ void prep_A_body(
    const float* __restrict__ X, uint32_t* __restrict__ H,
    uint32_t* __restrict__ L, int ROWS16, int K)
{
    const int t = blockIdx.x * blockDim.x + threadIdx.x;
    const int lane = t & 31, fb = t >> 5;
    const int m16 = fb % ROWS16, k16 = fb / ROWS16;
    const int g = lane >> 2, tt = lane & 3;
    uint32_t h[4], l[4];
    #pragma unroll
    for (int s = 0; s < 4; s++) {
        const int row = m16 * 16 + (s & 1) * 8 + g;
        const int kk  = k16 * 16 + (s >> 1) * 8 + 2 * tt;
        const float2 x = *(const float2*)&X[(size_t)row * K + kk];
        split_pack2(x.x, x.y, h[s], l[s]);
    }
    const size_t o = (size_t)(fb * 32 + lane) * 4;
    *(uint4*)&H[o] = make_uint4(h[0], h[1], h[2], h[3]);
    *(uint4*)&L[o] = make_uint4(l[0], l[1], l[2], l[3]);
}

__device__ __forceinline__ void prep_B_body(
    const float* __restrict__ X, uint32_t* __restrict__ H,
    uint32_t* __restrict__ L, int NROWS8, int K)
{
    const int t = blockIdx.x * blockDim.x + threadIdx.x;
    const int lane = t & 31, fb = t >> 5;
    const int n8 = fb % NROWS8, k16 = fb / NROWS8;
    const int g = lane >> 2, tt = lane & 3;
    uint32_t h[2], l[2];
    #pragma unroll
    for (int s = 0; s < 2; s++) {
        const int row = n8 * 8 + g;
        const int kk  = k16 * 16 + s * 8 + 2 * tt;
        const float2 x = *(const float2*)&X[(size_t)row * K + kk];
        split_pack2(x.x, x.y, h[s], l[s]);
    }
    const size_t o = (size_t)(fb * 32 + lane) * 2;
    *(uint2*)&H[o] = make_uint2(h[0], h[1]);
    *(uint2*)&L[o] = make_uint2(l[0], l[1]);
}

// Wrappers: bind __device__ frag buffers in DEVICE code (host may not take
// their address). Only harness-provided pointers cross the launch boundary.
__global__ void prep_u (const float* __restrict__ X) { prep_A_body(X, uA_h, uA_l, 64,  DL); }
__global__ void prep_v (const float* __restrict__ X) { prep_A_body(X, vA_h, vA_l, 256, DR); }
__global__ void prep_wu(const float* __restrict__ X) { prep_B_body(X, WuB_h, WuB_l, 32, DL); }
__global__ void prep_wv(const float* __restrict__ X) { prep_B_body(X, WvB_h, WvB_l, 32, DR); }
__global__ void prep_wp(const float* __restrict__ X) { prep_B_body(X, WpB_h, WpB_l, 32, DK); }

// ---- GEMM core ----
// TM x TN CTA tile, WM x WN warps, BK=32.
// A_COPY: A from pre-permuted global frags; else fp32 A (row stride KDIM) scaled by ws.
template <int TM, int TN, int WM, int WN, int KDIM, int AROWS, int NROWS,
          bool A_COPY, bool RELU>
__device__ __forceinline__ void gemm_core(
    const uint32_t* __restrict__ Agh, const uint32_t* __restrict__ Agl,
    const float* __restrict__ Afp,
    const uint32_t* __restrict__ Bgh, const uint32_t* __restrict__ Bgl,
    const float* __restrict__ wvec, const float* __restrict__ bias,
    float* __restrict__ C, int m0, int n0)
{
    constexpr int THREADS = WM * WN * 32;
    constexpr int MT = TM / WM / 16;       // m16 tiles per warp
    constexpr int NT = TN / WN / 8;        // n8 tiles per warp
    constexpr int NC = KDIM / 32;
    constexpr int AW = TM * 16;            // words per A sub-buffer per chunk
    constexpr int BW = TN * 16;
    constexpr int M16 = TM / 16, N8 = TN / 8;

    extern __shared__ uint32_t smem[];
    float* ws = (float*)smem;              // [256]
    float* bs = (float*)(smem + 256);      // [128]
    constexpr int OFF = 384;
    constexpr int STAGE = 2 * AW + 2 * BW;

    const int tid = threadIdx.x;
    const int wid = tid >> 5, lane = tid & 31;
    const int wm = wid % WM, wn = wid / WM;

    if (!A_COPY) { if (tid < 256) ws[tid] = wvec[tid]; }
    if (RELU)    { if (tid < TN)  bs[tid] = bias[n0 + tid]; }
    if (!A_COPY || RELU) __syncthreads();

    float c[MT][NT][4] = {};

    auto stage_chunk = [&](int ck, int st) {
        uint32_t* sAh = smem + OFF + st * STAGE;
        uint32_t* sAl = sAh + AW;
        uint32_t* sBh = sAl + AW;
        uint32_t* sBl = sBh + BW;
        // A
        if (A_COPY) {
            constexpr int AU4 = AW / (4 * THREADS);
            #pragma unroll
            for (int j = 0; j < AU4; j++) {
                const int w = (j * THREADS + tid) * 4;
                const int lb = w >> 7, off = w & 127;
                const int k16h = lb / M16, m16l = lb % M16;
                const size_t gw = ((size_t)(2 * ck + k16h) * (AROWS / 16) + m0 / 16 + m16l) * 128 + off;
                *(uint4*)&sAh[w] = *(const uint4*)&Agh[gw];
                *(uint4*)&sAl[w] = *(const uint4*)&Agl[gw];
            }
        } else {
            constexpr int FJ = (TM * 32 / 4) / THREADS;   // float4 per thread
            const int kt = ck * 32;
            #pragma unroll
            for (int j = 0; j < FJ; j++) {
                const int i = j * THREADS + tid;
                const int row = i >> 3, c4 = i & 7;
                float4 va = *(const float4*)&Afp[(size_t)row * KDIM + kt + c4 * 4];
                const float4 w4 = *(const float4*)&ws[kt + c4 * 4];
                va.x *= w4.x; va.y *= w4.y; va.z *= w4.z; va.w *= w4.w;
                const int kc = c4 >> 2, reg = (c4 >> 1) & 1, lp = (c4 & 1) * 2;
                const int mt = row >> 4, r = row & 15, half = r >> 3, g = r & 7;
                const int a0 = ((kc * M16 + mt) * 32 + g * 4 + lp) * 4 + half + 2 * reg;
                uint32_t h0, l0, h1, l1;
                split_pack2(va.x, va.y, h0, l0);
                split_pack2(va.z, va.w, h1, l1);
                sAh[a0] = h0; sAh[a0 + 4] = h1;
                sAl[a0] = l0; sAl[a0 + 4] = l1;
            }
        }
        // B (always copy from pre-permuted frags)
        {
            constexpr int BU4 = BW / (4 * THREADS);
            #pragma unroll
            for (int j = 0; j < BU4; j++) {
                const int w = (j * THREADS + tid) * 4;
                const int lb = w >> 6, off = w & 63;
                const int k16h = lb / N8, n8l = lb % N8;
                const size_t gw = ((size_t)(2 * ck + k16h) * (NROWS / 8) + n0 / 8 + n8l) * 64 + off;
                *(uint4*)&sBh[w] = *(const uint4*)&Bgh[gw];
                *(uint4*)&sBl[w] = *(const uint4*)&Bgl[gw];
            }
        }
    };

    auto compute_chunk = [&](int st) {
        const uint32_t* sAh = smem + OFF + st * STAGE;
        const uint32_t* sAl = sAh + AW;
        const uint32_t* sBh = sAl + AW;
        const uint32_t* sBl = sBh + BW;
        #pragma unroll
        for (int kc = 0; kc < 2; kc++) {
            uint32_t ah[MT][4], al[MT][4];
            #pragma unroll
            for (int mt = 0; mt < MT; mt++) {
                const int base = ((kc * M16 + wm * MT + mt) * 32 + lane) * 4;
                const uint4 vh = *(const uint4*)&sAh[base];
                ah[mt][0] = vh.x; ah[mt][1] = vh.y; ah[mt][2] = vh.z; ah[mt][3] = vh.w;
                const uint4 vl = *(const uint4*)&sAl[base];
                al[mt][0] = vl.x; al[mt][1] = vl.y; al[mt][2] = vl.z; al[mt][3] = vl.w;
            }
            uint32_t bh[NT][2], bl[NT][2];
            #pragma unroll
            for (int j = 0; j < NT; j++) {
                const int base = ((kc * N8 + wn * NT + j) * 32 + lane) * 2;
                const uint2 vh = *(const uint2*)&sBh[base];
                bh[j][0] = vh.x; bh[j][1] = vh.y;
                const uint2 vl = *(const uint2*)&sBl[base];
                bl[j][0] = vl.x; bl[j][1] = vl.y;
            }
            #pragma unroll
            for (int mt = 0; mt < MT; mt++)
                #pragma unroll
                for (int j = 0; j < NT; j++) {
                    mma_fp16(c[mt][j], ah[mt], bh[j]);
                    mma_fp16(c[mt][j], al[mt], bh[j]);
                    mma_fp16(c[mt][j], ah[mt], bl[j]);
                }
        }
    };

    stage_chunk(0, 0);
    __syncthreads();
    for (int ck = 0; ck < NC; ck++) {
        const int par = ck & 1;
        if (ck + 1 < NC) stage_chunk(ck + 1, par ^ 1);
        compute_chunk(par);
        __syncthreads();
    }

    const int g = lane >> 2, t = lane & 3;
    #pragma unroll
    for (int mt = 0; mt < MT; mt++) {
        const int row0 = wm * MT * 16 + mt * 16 + g;
        #pragma unroll
        for (int j = 0; j < NT; j++) {
            const int col = wn * NT * 8 + j * 8 + t * 2;
            float2 v0 = make_float2(c[mt][j][0], c[mt][j][1]);
            float2 v1 = make_float2(c[mt][j][2], c[mt][j][3]);
            if (RELU) {
                const float b0 = bs[col], b1 = bs[col + 1];
                v0.x = fmaxf(v0.x + b0, 0.0f); v0.y = fmaxf(v0.y + b1, 0.0f);
                v1.x = fmaxf(v1.x + b0, 0.0f); v1.y = fmaxf(v1.y + b1, 0.0f);
            }
            *(float2*)&C[(size_t)(m0 + row0) * 256 + n0 + col]     = v0;
            *(float2*)&C[(size_t)(m0 + row0 + 8) * 256 + n0 + col] = v1;
        }
    }
}

// k1: up[1024,256] = u @ Wu^T. Tiles 64x32, 128 thr, grid (8, 16) = 128 CTAs.
__global__ __launch_bounds__(128, 4) void k1_up() {
    gemm_core<64, 32, 2, 2, DL, 1024, DK, true, false>(
        uA_h, uA_l, nullptr, WuB_h, WuB_l, nullptr, nullptr,
        g_up, blockIdx.y * 64, blockIdx.x * 32);
}

// k2: vp[4096,256] = v @ Wv^T. Tiles 64x64, 128 thr, grid (4, 64) = 256 CTAs.
__global__ __launch_bounds__(128, 4) void k2_vp() {
    gemm_core<64, 64, 2, 2, DR, Bsz * Rr, DK, true, false>(
        vA_h, vA_l, nullptr, WvB_h, WvB_l, nullptr, nullptr,
        g_vp, blockIdx.y * 64, blockIdx.x * 64);
}

// k3: per bm: out = relu((vp[b]*diag(up[bm])) @ Wp^T + bp). 128x128, 512 thr.
__global__ __launch_bounds__(512, 1) void k3_fuse(const float* __restrict__ bp,
                                                  float* __restrict__ out) {
    const int bm = blockIdx.y, b = bm >> 5;
    gemm_core<128, 128, 4, 4, DK, Rr, DF, false, true>(
        nullptr, nullptr, g_vp + (size_t)b * Rr * DK,
        WpB_h, WpB_l, g_up + (size_t)bm * DK, bp,
        out + (size_t)bm * Rr * DF, 0, blockIdx.x * 128);
}

constexpr int SMEM_K1 = (384 + 2 * (2 * 64 * 16 + 2 * 32 * 16)) * 4;    // 26112
constexpr int SMEM_K2 = (384 + 2 * (2 * 64 * 16 + 2 * 64 * 16)) * 4;    // 34304
constexpr int SMEM_K3 = (384 + 2 * (2 * 128 * 16 + 2 * 128 * 16)) * 4;  // 67072

} // namespace

extern "C" void kernel_launch(void* const* d_in, const int* in_sizes, int n_in,
                              void* d_out, int out_size)
{
    (void)in_sizes; (void)n_in; (void)out_size;
    const float* u  = (const float*)d_in[0];   // (32, 32, 1024)
    const float* v  = (const float*)d_in[1];   // (32, 128, 2048)
    const float* Wu = (const float*)d_in[2];   // (256, 1024)
    const float* Wv = (const float*)d_in[3];   // (256, 2048)
    const float* Wp = (const float*)d_in[4];   // (256, 256)
    const float* bp = (const float*)d_in[5];   // (256,)
    float* out = (float*)d_out;                // (32, 32, 128, 256)

    cudaFuncSetAttribute(k1_up,   cudaFuncAttributeMaxDynamicSharedMemorySize, SMEM_K1);
    cudaFuncSetAttribute(k2_vp,   cudaFuncAttributeMaxDynamicSharedMemorySize, SMEM_K2);
    cudaFuncSetAttribute(k3_fuse, cudaFuncAttributeMaxDynamicSharedMemorySize, SMEM_K3);

    // prep: split+permute all static operands (grids = #frag_blocks * 32 / 256)
    prep_u <<<(64 * 64 * 32)  / 256, 256>>>(u);    // u: 1024x1024
    prep_v <<<(256 * 128 * 32) / 256, 256>>>(v);   // v: 4096x2048
    prep_wu<<<(32 * 64 * 32)  / 256, 256>>>(Wu);   // Wu: 256x1024
    prep_wv<<<(32 * 128 * 32) / 256, 256>>>(Wv);   // Wv: 256x2048
    prep_wp<<<(32 * 16 * 32)  / 256, 256>>>(Wp);   // Wp: 256x256

    k1_up<<<dim3(8, 16), 128, SMEM_K1>>>();             // 128 CTAs
    k2_vp<<<dim3(4, 64), 128, SMEM_K2>>>();             // 256 CTAs
    k3_fuse<<<dim3(2, 1024), 512, SMEM_K3>>>(bp, out);  // 2048 CTAs
}

// round 8
// speedup vs baseline: 2.8881x; 1.3153x over previous
#include <cuda_runtime.h>
#include <cuda_fp16.h>
#include <cstdint>

// LowRankBilinearFusion via fp16x3 split mma.sync with pre-permuted global
// fragment buffers + cp.async staging. C = A@B^T as Ah*Bh + Al*Bh + Ah*Bl.
//
// Fragment-permuted layouts (mma.m16n8k16.row.col):
//  A word idx: ((k16*(ROWS/16)+m16)*32+lane)*4+s, s in 0..3:
//    half2{ X[m16*16+(s&1)*8+g][k16*16+(s>>1)*8+2t], X[..+1] }, g=lane>>2, t=lane&3
//  B word idx: ((k16*(NROWS/8)+n8)*32+lane)*2+s, s in 0..1:
//    half2{ X[n8*8+g][k16*16+s*8+2t], X[..+1] }

namespace {

constexpr int Bsz = 32, Mq = 32, Rr = 128;
constexpr int DL = 1024, DR = 2048, DK = 256, DF = 256;

// ---- global scratch (device-code references only) ----
__device__ float g_up[Bsz * Mq * DK];
__device__ float g_vp[Bsz * Rr * DK];
__device__ uint32_t uA_h[DL * Bsz * Mq / 2],  uA_l[DL * Bsz * Mq / 2];
__device__ uint32_t vA_h[(size_t)Bsz * Rr * DR / 2], vA_l[(size_t)Bsz * Rr * DR / 2];
__device__ uint32_t WuB_h[DK * DL / 2], WuB_l[DK * DL / 2];
__device__ uint32_t WvB_h[DK * DR / 2], WvB_l[DK * DR / 2];
__device__ uint32_t WpB_h[DF * DK / 2], WpB_l[DF * DK / 2];

__device__ __forceinline__ void mma_fp16(float* c, const uint32_t* a, const uint32_t* b) {
    asm volatile(
        "mma.sync.aligned.m16n8k16.row.col.f32.f16.f16.f32 "
        "{%0,%1,%2,%3}, {%4,%5,%6,%7}, {%8,%9}, {%0,%1,%2,%3};"
        : "+f"(c[0]), "+f"(c[1]), "+f"(c[2]), "+f"(c[3])
        : "r"(a[0]), "r"(a[1]), "r"(a[2]), "r"(a[3]), "r"(b[0]), "r"(b[1]));
}

__device__ __forceinline__ void split2(float x, __half& hi, __half& lo) {
    hi = __float2half_rn(x);
    lo = __float2half_rn(x - __half2float(hi));
}
__device__ __forceinline__ uint32_t pack2(__half a, __half b) {
    return (uint32_t)__half_as_ushort(a) | ((uint32_t)__half_as_ushort(b) << 16);
}
__device__ __forceinline__ void split_pack2(float x0, float x1, uint32_t& h, uint32_t& l) {
    __half h0, l0, h1, l1;
    split2(x0, h0, l0); split2(x1, h1, l1);
    h = pack2(h0, h1); l = pack2(l0, l1);
}

__device__ __forceinline__ void cp16(void* sdst, const void* gsrc) {
    uint32_t sa = (uint32_t)__cvta_generic_to_shared(sdst);
    asm volatile("cp.async.cg.shared.global [%0], [%1], 16;" :: "r"(sa), "l"(gsrc) : "memory");
}
#define CP_COMMIT() asm volatile("cp.async.commit_group;" ::: "memory")
#define CP_WAIT0()  asm volatile("cp.async.wait_group 0;"  ::: "memory")

// ---- prep: fp32 row-major -> permuted hi/lo fp16 frag buffers ----
__device__ __forceinline__ void prep_A_body(
    const float* __restrict__ X, uint32_t* __restrict__ H,
    uint32_t* __restrict__ L, int ROWS16, int K)
{
    const int t = blockIdx.x * blockDim.x + threadIdx.x;
    const int lane = t & 31, fb = t >> 5;
    const int m16 = fb % ROWS16, k16 = fb / ROWS16;
    const int g = lane >> 2, tt = lane & 3;
    uint32_t h[4], l[4];
    #pragma unroll
    for (int s = 0; s < 4; s++) {
        const int row = m16 * 16 + (s & 1) * 8 + g;
        const int kk  = k16 * 16 + (s >> 1) * 8 + 2 * tt;
        const float2 x = *(const float2*)&X[(size_t)row * K + kk];
        split_pack2(x.x, x.y, h[s], l[s]);
    }
    const size_t o = (size_t)(fb * 32 + lane) * 4;
    *(uint4*)&H[o] = make_uint4(h[0], h[1], h[2], h[3]);
    *(uint4*)&L[o] = make_uint4(l[0], l[1], l[2], l[3]);
}

__device__ __forceinline__ void prep_B_body(
    const float* __restrict__ X, uint32_t* __restrict__ H,
    uint32_t* __restrict__ L, int NROWS8, int K)
{
    const int t = blockIdx.x * blockDim.x + threadIdx.x;
    const int lane = t & 31, fb = t >> 5;
    const int n8 = fb % NROWS8, k16 = fb / NROWS8;
    const int g = lane >> 2, tt = lane & 3;
    uint32_t h[2], l[2];
    #pragma unroll
    for (int s = 0; s < 2; s++) {
        const int row = n8 * 8 + g;
        const int kk  = k16 * 16 + s * 8 + 2 * tt;
        const float2 x = *(const float2*)&X[(size_t)row * K + kk];
        split_pack2(x.x, x.y, h[s], l[s]);
    }
    const size_t o = (size_t)(fb * 32 + lane) * 2;
    *(uint2*)&H[o] = make_uint2(h[0], h[1]);
    *(uint2*)&L[o] = make_uint2(l[0], l[1]);
}

__global__ void prep_u (const float* __restrict__ X) { prep_A_body(X, uA_h, uA_l, 64,  DL); }
__global__ void prep_v (const float* __restrict__ X) { prep_A_body(X, vA_h, vA_l, 256, DR); }
__global__ void prep_wu(const float* __restrict__ X) { prep_B_body(X, WuB_h, WuB_l, 32, DL); }
__global__ void prep_wv(const float* __restrict__ X) { prep_B_body(X, WvB_h, WvB_l, 32, DR); }
__global__ void prep_wp(const float* __restrict__ X) { prep_B_body(X, WpB_h, WpB_l, 32, DK); }

// ---- GEMM core ----
template <int TM, int TN, int WM, int WN, int KDIM, int AROWS, int NROWS,
          bool A_COPY, bool RELU>
__device__ __forceinline__ void gemm_core(
    const uint32_t* __restrict__ Agh, const uint32_t* __restrict__ Agl,
    const float* __restrict__ Afp,
    const uint32_t* __restrict__ Bgh, const uint32_t* __restrict__ Bgl,
    const float* __restrict__ wvec, const float* __restrict__ bias,
    float* __restrict__ C, int m0, int n0)
{
    constexpr int THREADS = WM * WN * 32;
    constexpr int MT = TM / WM / 16;
    constexpr int NT = TN / WN / 8;
    constexpr int NC = KDIM / 32;
    constexpr int AW = TM * 16;            // words per A sub-buffer per chunk
    constexpr int BW = TN * 16;
    constexpr int M16 = TM / 16, N8 = TN / 8;

    extern __shared__ uint32_t smem[];
    float* ws = (float*)smem;              // [256]
    float* bs = (float*)(smem + 256);      // [256]
    constexpr int OFF = 512;
    constexpr int STAGE = 2 * AW + 2 * BW;

    const int tid = threadIdx.x;
    const int wid = tid >> 5, lane = tid & 31;
    const int wm = wid % WM, wn = wid / WM;

    if (!A_COPY) { if (tid < 256) ws[tid] = wvec[tid]; }
    if (RELU)    { if (tid < TN)  bs[tid] = bias[n0 + tid]; }
    if (!A_COPY || RELU) __syncthreads();

    float c[MT][NT][4] = {};

    auto stage_chunk = [&](int ck, int st) {
        uint32_t* sAh = smem + OFF + st * STAGE;
        uint32_t* sAl = sAh + AW;
        uint32_t* sBh = sAl + AW;
        uint32_t* sBl = sBh + BW;
        // A
        if (A_COPY) {
            constexpr int AU4 = AW / (4 * THREADS);
            #pragma unroll
            for (int j = 0; j < AU4; j++) {
                const int w = (j * THREADS + tid) * 4;
                const int lb = w >> 7, off = w & 127;
                const int k16h = lb / M16, m16l = lb % M16;
                const size_t gw = ((size_t)(2 * ck + k16h) * (AROWS / 16) + m0 / 16 + m16l) * 128 + off;
                cp16(&sAh[w], &Agh[gw]);
                cp16(&sAl[w], &Agl[gw]);
            }
        } else {
            constexpr int FJ = (TM * 32 / 4) / THREADS;
            const int kt = ck * 32;
            #pragma unroll
            for (int j = 0; j < FJ; j++) {
                const int i = j * THREADS + tid;
                const int row = i >> 3, c4 = i & 7;
                float4 va = *(const float4*)&Afp[(size_t)row * KDIM + kt + c4 * 4];
                const float4 w4 = *(const float4*)&ws[kt + c4 * 4];
                va.x *= w4.x; va.y *= w4.y; va.z *= w4.z; va.w *= w4.w;
                const int kc = c4 >> 2, reg = (c4 >> 1) & 1, lp = (c4 & 1) * 2;
                const int mt = row >> 4, r = row & 15, half = r >> 3, g = r & 7;
                const int a0 = ((kc * M16 + mt) * 32 + g * 4 + lp) * 4 + half + 2 * reg;
                uint32_t h0, l0, h1, l1;
                split_pack2(va.x, va.y, h0, l0);
                split_pack2(va.z, va.w, h1, l1);
                sAh[a0] = h0; sAh[a0 + 4] = h1;
                sAl[a0] = l0; sAl[a0 + 4] = l1;
            }
        }
        // B (always pure copy of pre-permuted frags)
        {
            constexpr int BU4 = BW / (4 * THREADS);
            #pragma unroll
            for (int j = 0; j < BU4; j++) {
                const int w = (j * THREADS + tid) * 4;
                const int lb = w >> 6, off = w & 63;
                const int k16h = lb / N8, n8l = lb % N8;
                const size_t gw = ((size_t)(2 * ck + k16h) * (NROWS / 8) + n0 / 8 + n8l) * 64 + off;
                cp16(&sBh[w], &Bgh[gw]);
                cp16(&sBl[w], &Bgl[gw]);
            }
        }
    };

    auto compute_chunk = [&](int st) {
        const uint32_t* sAh = smem + OFF + st * STAGE;
        const uint32_t* sAl = sAh + AW;
        const uint32_t* sBh = sAl + AW;
        const uint32_t* sBl = sBh + BW;
        #pragma unroll
        for (int kc = 0; kc < 2; kc++) {
            uint32_t ah[MT][4], al[MT][4];
            #pragma unroll
            for (int mt = 0; mt < MT; mt++) {
                const int base = ((kc * M16 + wm * MT + mt) * 32 + lane) * 4;
                const uint4 vh = *(const uint4*)&sAh[base];
                ah[mt][0] = vh.x; ah[mt][1] = vh.y; ah[mt][2] = vh.z; ah[mt][3] = vh.w;
                const uint4 vl = *(const uint4*)&sAl[base];
                al[mt][0] = vl.x; al[mt][1] = vl.y; al[mt][2] = vl.z; al[mt][3] = vl.w;
            }
            // b-fragments with one-j lookahead (keeps register pressure low)
            uint32_t bh[2][2], bl[2][2];
            {
                const int base = ((kc * N8 + wn * NT) * 32 + lane) * 2;
                const uint2 vh = *(const uint2*)&sBh[base]; bh[0][0] = vh.x; bh[0][1] = vh.y;
                const uint2 vl = *(const uint2*)&sBl[base]; bl[0][0] = vl.x; bl[0][1] = vl.y;
            }
            #pragma unroll
            for (int j = 0; j < NT; j++) {
                const int cur = j & 1, nxt = cur ^ 1;
                if (j + 1 < NT) {
                    const int base = ((kc * N8 + wn * NT + j + 1) * 32 + lane) * 2;
                    const uint2 vh = *(const uint2*)&sBh[base]; bh[nxt][0] = vh.x; bh[nxt][1] = vh.y;
                    const uint2 vl = *(const uint2*)&sBl[base]; bl[nxt][0] = vl.x; bl[nxt][1] = vl.y;
                }
                #pragma unroll
                for (int mt = 0; mt < MT; mt++) {
                    mma_fp16(c[mt][j], ah[mt], bh[cur]);
                    mma_fp16(c[mt][j], al[mt], bh[cur]);
                    mma_fp16(c[mt][j], ah[mt], bl[cur]);
                }
            }
        }
    };

    stage_chunk(0, 0);
    CP_COMMIT(); CP_WAIT0();
    __syncthreads();
    for (int ck = 0; ck < NC; ck++) {
        const int par = ck & 1;
        if (ck + 1 < NC) { stage_chunk(ck + 1, par ^ 1); CP_COMMIT(); }
        compute_chunk(par);
        CP_WAIT0();
        __syncthreads();
    }

    const int g = lane >> 2, t = lane & 3;
    #pragma unroll
    for (int mt = 0; mt < MT; mt++) {
        const int row0 = wm * MT * 16 + mt * 16 + g;
        #pragma unroll
        for (int j = 0; j < NT; j++) {
            const int col = wn * NT * 8 + j * 8 + t * 2;
            float2 v0 = make_float2(c[mt][j][0], c[mt][j][1]);
            float2 v1 = make_float2(c[mt][j][2], c[mt][j][3]);
            if (RELU) {
                const float b0 = bs[col], b1 = bs[col + 1];
                v0.x = fmaxf(v0.x + b0, 0.0f); v0.y = fmaxf(v0.y + b1, 0.0f);
                v1.x = fmaxf(v1.x + b0, 0.0f); v1.y = fmaxf(v1.y + b1, 0.0f);
            }
            *(float2*)&C[(size_t)(m0 + row0) * 256 + n0 + col]     = v0;
            *(float2*)&C[(size_t)(m0 + row0 + 8) * 256 + n0 + col] = v1;
        }
    }
}

// k1: up[1024,256] = u @ Wu^T. 64x32 tiles, 128 thr, grid (8,16).
__global__ __launch_bounds__(128, 4) void k1_up() {
    gemm_core<64, 32, 2, 2, DL, 1024, DK, true, false>(
        uA_h, uA_l, nullptr, WuB_h, WuB_l, nullptr, nullptr,
        g_up, blockIdx.y * 64, blockIdx.x * 32);
}

// k2: vp[4096,256] = v @ Wv^T. 64x64 tiles, 128 thr, grid (4,64).
__global__ __launch_bounds__(128, 4) void k2_vp() {
    gemm_core<64, 64, 2, 2, DR, Bsz * Rr, DK, true, false>(
        vA_h, vA_l, nullptr, WvB_h, WvB_l, nullptr, nullptr,
        g_vp, blockIdx.y * 64, blockIdx.x * 64);
}

// k3: per bm: out = relu((vp[b]*diag(up[bm])) @ Wp^T + bp). 128x256 tile, 512 thr.
__global__ __launch_bounds__(512, 1) void k3_fuse(const float* __restrict__ bp,
                                                  float* __restrict__ out) {
    const int bm = blockIdx.x, b = bm >> 5;
    gemm_core<128, 256, 4, 4, DK, Rr, DF, false, true>(
        nullptr, nullptr, g_vp + (size_t)b * Rr * DK,
        WpB_h, WpB_l, g_up + (size_t)bm * DK, bp,
        out + (size_t)bm * Rr * DF, 0, 0);
}

constexpr int SMEM_K1 = (512 + 2 * (2 * 64 * 16 + 2 * 32 * 16)) * 4;    // 26624
constexpr int SMEM_K2 = (512 + 2 * (2 * 64 * 16 + 2 * 64 * 16)) * 4;    // 34816
constexpr int SMEM_K3 = (512 + 2 * (2 * 128 * 16 + 2 * 256 * 16)) * 4;  // 100352

} // namespace

extern "C" void kernel_launch(void* const* d_in, const int* in_sizes, int n_in,
                              void* d_out, int out_size)
{
    (void)in_sizes; (void)n_in; (void)out_size;
    const float* u  = (const float*)d_in[0];   // (32, 32, 1024)
    const float* v  = (const float*)d_in[1];   // (32, 128, 2048)
    const float* Wu = (const float*)d_in[2];   // (256, 1024)
    const float* Wv = (const float*)d_in[3];   // (256, 2048)
    const float* Wp = (const float*)d_in[4];   // (256, 256)
    const float* bp = (const float*)d_in[5];   // (256,)
    float* out = (float*)d_out;                // (32, 32, 128, 256)

    cudaFuncSetAttribute(k1_up,   cudaFuncAttributeMaxDynamicSharedMemorySize, SMEM_K1);
    cudaFuncSetAttribute(k2_vp,   cudaFuncAttributeMaxDynamicSharedMemorySize, SMEM_K2);
    cudaFuncSetAttribute(k3_fuse, cudaFuncAttributeMaxDynamicSharedMemorySize, SMEM_K3);

    prep_u <<<(64 * 64 * 32)   / 256, 256>>>(u);
    prep_v <<<(256 * 128 * 32) / 256, 256>>>(v);
    prep_wu<<<(32 * 64 * 32)   / 256, 256>>>(Wu);
    prep_wv<<<(32 * 128 * 32)  / 256, 256>>>(Wv);
    prep_wp<<<(32 * 16 * 32)   / 256, 256>>>(Wp);

    k1_up<<<dim3(8, 16), 128, SMEM_K1>>>();           // 128 CTAs
    k2_vp<<<dim3(4, 64), 128, SMEM_K2>>>();           // 256 CTAs
    k3_fuse<<<1024, 512, SMEM_K3>>>(bp, out);         // 1024 CTAs
}

// round 9
// speedup vs baseline: 3.0090x; 1.0419x over previous
#include <cuda_runtime.h>
#include <cuda_fp16.h>
#include <cstdint>

// LowRankBilinearFusion via fp16x3 split mma.sync with pre-permuted global
// fragment buffers + cp.async staging. C = A@B^T as Ah*Bh + Al*Bh + Ah*Bl.
//
// Fragment-permuted layouts (mma.m16n8k16.row.col):
//  A word idx: ((k16*(ROWS/16)+m16)*32+lane)*4+s, s in 0..3:
//    half2{ X[m16*16+(s&1)*8+g][k16*16+(s>>1)*8+2t], X[..+1] }, g=lane>>2, t=lane&3
//  B word idx: ((k16*(NROWS/8)+n8)*32+lane)*2+s, s in 0..1:
//    half2{ X[n8*8+g][k16*16+s*8+2t], X[..+1] }

namespace {

constexpr int Bsz = 32, Mq = 32, Rr = 128;
constexpr int DL = 1024, DR = 2048, DK = 256, DF = 256;

// ---- global scratch (device-code references only) ----
__device__ float g_up[Bsz * Mq * DK];
__device__ float g_vp[Bsz * Rr * DK];
__device__ uint32_t uA_h[DL * Bsz * Mq / 2],  uA_l[DL * Bsz * Mq / 2];
__device__ uint32_t vA_h[(size_t)Bsz * Rr * DR / 2], vA_l[(size_t)Bsz * Rr * DR / 2];
__device__ uint32_t WuB_h[DK * DL / 2], WuB_l[DK * DL / 2];
__device__ uint32_t WvB_h[DK * DR / 2], WvB_l[DK * DR / 2];
__device__ uint32_t WpB_h[DF * DK / 2], WpB_l[DF * DK / 2];

__device__ __forceinline__ void mma_fp16(float* c, const uint32_t* a, const uint32_t* b) {
    asm volatile(
        "mma.sync.aligned.m16n8k16.row.col.f32.f16.f16.f32 "
        "{%0,%1,%2,%3}, {%4,%5,%6,%7}, {%8,%9}, {%0,%1,%2,%3};"
        : "+f"(c[0]), "+f"(c[1]), "+f"(c[2]), "+f"(c[3])
        : "r"(a[0]), "r"(a[1]), "r"(a[2]), "r"(a[3]), "r"(b[0]), "r"(b[1]));
}

__device__ __forceinline__ void split2(float x, __half& hi, __half& lo) {
    hi = __float2half_rn(x);
    lo = __float2half_rn(x - __half2float(hi));
}
__device__ __forceinline__ uint32_t pack2(__half a, __half b) {
    return (uint32_t)__half_as_ushort(a) | ((uint32_t)__half_as_ushort(b) << 16);
}
__device__ __forceinline__ void split_pack2(float x0, float x1, uint32_t& h, uint32_t& l) {
    __half h0, l0, h1, l1;
    split2(x0, h0, l0); split2(x1, h1, l1);
    h = pack2(h0, h1); l = pack2(l0, l1);
}

__device__ __forceinline__ void cp16(void* sdst, const void* gsrc) {
    uint32_t sa = (uint32_t)__cvta_generic_to_shared(sdst);
    asm volatile("cp.async.cg.shared.global [%0], [%1], 16;" :: "r"(sa), "l"(gsrc) : "memory");
}
#define CP_COMMIT() asm volatile("cp.async.commit_group;" ::: "memory")
#define CP_WAIT0()  asm volatile("cp.async.wait_group 0;"  ::: "memory")

// ---- prep: fp32 row-major -> permuted hi/lo fp16 frag buffers ----
__device__ __forceinline__ void prep_A_body(
    const float* __restrict__ X, uint32_t* __restrict__ H,
    uint32_t* __restrict__ L, int ROWS16, int K)
{
    const int t = blockIdx.x * blockDim.x + threadIdx.x;
    const int lane = t & 31, fb = t >> 5;
    const int m16 = fb % ROWS16, k16 = fb / ROWS16;
    const int g = lane >> 2, tt = lane & 3;
    uint32_t h[4], l[4];
    #pragma unroll
    for (int s = 0; s < 4; s++) {
        const int row = m16 * 16 + (s & 1) * 8 + g;
        const int kk  = k16 * 16 + (s >> 1) * 8 + 2 * tt;
        const float2 x = *(const float2*)&X[(size_t)row * K + kk];
        split_pack2(x.x, x.y, h[s], l[s]);
    }
    const size_t o = (size_t)(fb * 32 + lane) * 4;
    *(uint4*)&H[o] = make_uint4(h[0], h[1], h[2], h[3]);
    *(uint4*)&L[o] = make_uint4(l[0], l[1], l[2], l[3]);
}

__device__ __forceinline__ void prep_B_body(
    const float* __restrict__ X, uint32_t* __restrict__ H,
    uint32_t* __restrict__ L, int NROWS8, int K)
{
    const int t = blockIdx.x * blockDim.x + threadIdx.x;
    const int lane = t & 31, fb = t >> 5;
    const int n8 = fb % NROWS8, k16 = fb / NROWS8;
    const int g = lane >> 2, tt = lane & 3;
    uint32_t h[2], l[2];
    #pragma unroll
    for (int s = 0; s < 2; s++) {
        const int row = n8 * 8 + g;
        const int kk  = k16 * 16 + s * 8 + 2 * tt;
        const float2 x = *(const float2*)&X[(size_t)row * K + kk];
        split_pack2(x.x, x.y, h[s], l[s]);
    }
    const size_t o = (size_t)(fb * 32 + lane) * 2;
    *(uint2*)&H[o] = make_uint2(h[0], h[1]);
    *(uint2*)&L[o] = make_uint2(l[0], l[1]);
}

__global__ void prep_u (const float* __restrict__ X) { prep_A_body(X, uA_h, uA_l, 64,  DL); }
__global__ void prep_v (const float* __restrict__ X) { prep_A_body(X, vA_h, vA_l, 256, DR); }
__global__ void prep_wu(const float* __restrict__ X) { prep_B_body(X, WuB_h, WuB_l, 32, DL); }
__global__ void prep_wv(const float* __restrict__ X) { prep_B_body(X, WvB_h, WvB_l, 32, DR); }
__global__ void prep_wp(const float* __restrict__ X) { prep_B_body(X, WpB_h, WpB_l, 32, DK); }

// ---- GEMM core ----
template <int TM, int TN, int WM, int WN, int KDIM, int AROWS, int NROWS,
          bool A_COPY, bool RELU>
__device__ __forceinline__ void gemm_core(
    const uint32_t* __restrict__ Agh, const uint32_t* __restrict__ Agl,
    const float* __restrict__ Afp,
    const uint32_t* __restrict__ Bgh, const uint32_t* __restrict__ Bgl,
    const float* __restrict__ wvec, const float* __restrict__ bias,
    float* __restrict__ C, int m0, int n0)
{
    constexpr int THREADS = WM * WN * 32;
    constexpr int MT = TM / WM / 16;
    constexpr int NT = TN / WN / 8;
    constexpr int NC = KDIM / 32;
    constexpr int AW = TM * 16;            // words per A sub-buffer per chunk
    constexpr int BW = TN * 16;
    constexpr int M16 = TM / 16, N8 = TN / 8;
    constexpr int FJ = (TM * 32 / 4) / THREADS;   // fp32-A float4 per thread

    extern __shared__ uint32_t smem[];
    float* ws = (float*)smem;              // [256]
    float* bs = (float*)(smem + 256);      // [256]
    constexpr int OFF = 512;
    constexpr int STAGE = 2 * AW + 2 * BW;

    const int tid = threadIdx.x;
    const int wid = tid >> 5, lane = tid & 31;
    const int wm = wid % WM, wn = wid / WM;

    if (!A_COPY) { if (tid < 256) ws[tid] = wvec[tid]; }
    if (RELU)    { if (tid < TN)  bs[tid] = bias[n0 + tid]; }
    if (!A_COPY || RELU) __syncthreads();

    float c[MT][NT][4] = {};
    float4 ar[FJ];   // fp32-A register prefetch buffer

    // issue fp32-A global loads for chunk ck into ar (latency hidden by caller)
    auto ldgA = [&](int ck) {
        const int kt = ck * 32;
        #pragma unroll
        for (int j = 0; j < FJ; j++) {
            const int i = j * THREADS + tid;
            const int row = i >> 3, c4 = i & 7;
            ar[j] = *(const float4*)&Afp[(size_t)row * KDIM + kt + c4 * 4];
        }
    };
    // scale + split + STS the prefetched ar into stage st
    auto stsA = [&](int ck, int st) {
        uint32_t* sAh = smem + OFF + st * STAGE;
        uint32_t* sAl = sAh + AW;
        const int kt = ck * 32;
        #pragma unroll
        for (int j = 0; j < FJ; j++) {
            const int i = j * THREADS + tid;
            const int row = i >> 3, c4 = i & 7;
            float4 va = ar[j];
            const float4 w4 = *(const float4*)&ws[kt + c4 * 4];
            va.x *= w4.x; va.y *= w4.y; va.z *= w4.z; va.w *= w4.w;
            const int kc = c4 >> 2, reg = (c4 >> 1) & 1, lp = (c4 & 1) * 2;
            const int mt = row >> 4, r = row & 15, half = r >> 3, g = r & 7;
            const int a0 = ((kc * M16 + mt) * 32 + g * 4 + lp) * 4 + half + 2 * reg;
            uint32_t h0, l0, h1, l1;
            split_pack2(va.x, va.y, h0, l0);
            split_pack2(va.z, va.w, h1, l1);
            sAh[a0] = h0; sAh[a0 + 4] = h1;
            sAl[a0] = l0; sAl[a0 + 4] = l1;
        }
    };
    // cp.async A copy (pre-permuted frags)
    auto cpA = [&](int ck, int st) {
        uint32_t* sAh = smem + OFF + st * STAGE;
        uint32_t* sAl = sAh + AW;
        constexpr int AU4 = AW / (4 * THREADS);
        #pragma unroll
        for (int j = 0; j < AU4; j++) {
            const int w = (j * THREADS + tid) * 4;
            const int lb = w >> 7, off = w & 127;
            const int k16h = lb / M16, m16l = lb % M16;
            const size_t gw = ((size_t)(2 * ck + k16h) * (AROWS / 16) + m0 / 16 + m16l) * 128 + off;
            cp16(&sAh[w], &Agh[gw]);
            cp16(&sAl[w], &Agl[gw]);
        }
    };
    // cp.async B copy (pre-permuted frags)
    auto cpB = [&](int ck, int st) {
        uint32_t* sBh = smem + OFF + st * STAGE + 2 * AW;
        uint32_t* sBl = sBh + BW;
        constexpr int BU4 = BW / (4 * THREADS);
        #pragma unroll
        for (int j = 0; j < BU4; j++) {
            const int w = (j * THREADS + tid) * 4;
            const int lb = w >> 6, off = w & 63;
            const int k16h = lb / N8, n8l = lb % N8;
            const size_t gw = ((size_t)(2 * ck + k16h) * (NROWS / 8) + n0 / 8 + n8l) * 64 + off;
            cp16(&sBh[w], &Bgh[gw]);
            cp16(&sBl[w], &Bgl[gw]);
        }
    };

    auto compute_chunk = [&](int st) {
        const uint32_t* sAh = smem + OFF + st * STAGE;
        const uint32_t* sAl = sAh + AW;
        const uint32_t* sBh = sAl + AW;
        const uint32_t* sBl = sBh + BW;
        #pragma unroll
        for (int kc = 0; kc < 2; kc++) {
            uint32_t ah[MT][4], al[MT][4];
            #pragma unroll
            for (int mt = 0; mt < MT; mt++) {
                const int base = ((kc * M16 + wm * MT + mt) * 32 + lane) * 4;
                const uint4 vh = *(const uint4*)&sAh[base];
                ah[mt][0] = vh.x; ah[mt][1] = vh.y; ah[mt][2] = vh.z; ah[mt][3] = vh.w;
                const uint4 vl = *(const uint4*)&sAl[base];
                al[mt][0] = vl.x; al[mt][1] = vl.y; al[mt][2] = vl.z; al[mt][3] = vl.w;
            }
            uint32_t bh[2][2], bl[2][2];
            {
                const int base = ((kc * N8 + wn * NT) * 32 + lane) * 2;
                const uint2 vh = *(const uint2*)&sBh[base]; bh[0][0] = vh.x; bh[0][1] = vh.y;
                const uint2 vl = *(const uint2*)&sBl[base]; bl[0][0] = vl.x; bl[0][1] = vl.y;
            }
            #pragma unroll
            for (int j = 0; j < NT; j++) {
                const int cur = j & 1, nxt = cur ^ 1;
                if (j + 1 < NT) {
                    const int base = ((kc * N8 + wn * NT + j + 1) * 32 + lane) * 2;
                    const uint2 vh = *(const uint2*)&sBh[base]; bh[nxt][0] = vh.x; bh[nxt][1] = vh.y;
                    const uint2 vl = *(const uint2*)&sBl[base]; bl[nxt][0] = vl.x; bl[nxt][1] = vl.y;
                }
                #pragma unroll
                for (int mt = 0; mt < MT; mt++) {
                    mma_fp16(c[mt][j], ah[mt], bh[cur]);
                    mma_fp16(c[mt][j], al[mt], bh[cur]);
                    mma_fp16(c[mt][j], ah[mt], bl[cur]);
                }
            }
        }
    };

    // ---- prologue ----
    if (A_COPY) cpA(0, 0); else { ldgA(0); }
    cpB(0, 0); CP_COMMIT();
    if (!A_COPY) stsA(0, 0);
    CP_WAIT0();
    __syncthreads();

    // ---- main loop: A LDG issued BEFORE compute (latency hidden), STS after ----
    for (int ck = 0; ck < NC; ck++) {
        const int par = ck & 1;
        if (ck + 1 < NC) {
            if (A_COPY) cpA(ck + 1, par ^ 1); else ldgA(ck + 1);
            cpB(ck + 1, par ^ 1);
            CP_COMMIT();
        }
        compute_chunk(par);
        if (ck + 1 < NC && !A_COPY) stsA(ck + 1, par ^ 1);
        CP_WAIT0();
        __syncthreads();
    }

    const int g = lane >> 2, t = lane & 3;
    #pragma unroll
    for (int mt = 0; mt < MT; mt++) {
        const int row0 = wm * MT * 16 + mt * 16 + g;
        #pragma unroll
        for (int j = 0; j < NT; j++) {
            const int col = wn * NT * 8 + j * 8 + t * 2;
            float2 v0 = make_float2(c[mt][j][0], c[mt][j][1]);
            float2 v1 = make_float2(c[mt][j][2], c[mt][j][3]);
            if (RELU) {
                const float b0 = bs[col], b1 = bs[col + 1];
                v0.x = fmaxf(v0.x + b0, 0.0f); v0.y = fmaxf(v0.y + b1, 0.0f);
                v1.x = fmaxf(v1.x + b0, 0.0f); v1.y = fmaxf(v1.y + b1, 0.0f);
            }
            *(float2*)&C[(size_t)(m0 + row0) * 256 + n0 + col]     = v0;
            *(float2*)&C[(size_t)(m0 + row0 + 8) * 256 + n0 + col] = v1;
        }
    }
}

// k1: up[1024,256] = u @ Wu^T. 64x32 tiles, 128 thr, grid (8,16).
__global__ __launch_bounds__(128, 4) void k1_up() {
    gemm_core<64, 32, 2, 2, DL, 1024, DK, true, false>(
        uA_h, uA_l, nullptr, WuB_h, WuB_l, nullptr, nullptr,
        g_up, blockIdx.y * 64, blockIdx.x * 32);
}

// k2: vp[4096,256] = v @ Wv^T. 64x64 tiles, 128 thr, grid (4,64).
__global__ __launch_bounds__(128, 4) void k2_vp() {
    gemm_core<64, 64, 2, 2, DR, Bsz * Rr, DK, true, false>(
        vA_h, vA_l, nullptr, WvB_h, WvB_l, nullptr, nullptr,
        g_vp, blockIdx.y * 64, blockIdx.x * 64);
}

// k3: per bm: out = relu((vp[b]*diag(up[bm])) @ Wp^T + bp). 128x256 tile, 512 thr.
__global__ __launch_bounds__(512, 1) void k3_fuse(const float* __restrict__ bp,
                                                  float* __restrict__ out) {
    const int bm = blockIdx.x, b = bm >> 5;
    gemm_core<128, 256, 4, 4, DK, Rr, DF, false, true>(
        nullptr, nullptr, g_vp + (size_t)b * Rr * DK,
        WpB_h, WpB_l, g_up + (size_t)bm * DK, bp,
        out + (size_t)bm * Rr * DF, 0, 0);
}

constexpr int SMEM_K1 = (512 + 2 * (2 * 64 * 16 + 2 * 32 * 16)) * 4;    // 26624
constexpr int SMEM_K2 = (512 + 2 * (2 * 64 * 16 + 2 * 64 * 16)) * 4;    // 34816
constexpr int SMEM_K3 = (512 + 2 * (2 * 128 * 16 + 2 * 256 * 16)) * 4;  // 100352

} // namespace

extern "C" void kernel_launch(void* const* d_in, const int* in_sizes, int n_in,
                              void* d_out, int out_size)
{
    (void)in_sizes; (void)n_in; (void)out_size;
    const float* u  = (const float*)d_in[0];   // (32, 32, 1024)
    const float* v  = (const float*)d_in[1];   // (32, 128, 2048)
    const float* Wu = (const float*)d_in[2];   // (256, 1024)
    const float* Wv = (const float*)d_in[3];   // (256, 2048)
    const float* Wp = (const float*)d_in[4];   // (256, 256)
    const float* bp = (const float*)d_in[5];   // (256,)
    float* out = (float*)d_out;                // (32, 32, 128, 256)

    cudaFuncSetAttribute(k1_up,   cudaFuncAttributeMaxDynamicSharedMemorySize, SMEM_K1);
    cudaFuncSetAttribute(k2_vp,   cudaFuncAttributeMaxDynamicSharedMemorySize, SMEM_K2);
    cudaFuncSetAttribute(k3_fuse, cudaFuncAttributeMaxDynamicSharedMemorySize, SMEM_K3);

    prep_u <<<(64 * 64 * 32)   / 256, 256>>>(u);
    prep_v <<<(256 * 128 * 32) / 256, 256>>>(v);
    prep_wu<<<(32 * 64 * 32)   / 256, 256>>>(Wu);
    prep_wv<<<(32 * 128 * 32)  / 256, 256>>>(Wv);
    prep_wp<<<(32 * 16 * 32)   / 256, 256>>>(Wp);

    k1_up<<<dim3(8, 16), 128, SMEM_K1>>>();           // 128 CTAs
    k2_vp<<<dim3(4, 64), 128, SMEM_K2>>>();           // 256 CTAs
    k3_fuse<<<1024, 512, SMEM_K3>>>(bp, out);         // 1024 CTAs
}

// round 10
// speedup vs baseline: 3.4702x; 1.1533x over previous
#include <cuda_runtime.h>
#include <cuda_fp16.h>
#include <cstdint>

// LowRankBilinearFusion via fp16-split mma.sync with pre-permuted global
// fragment buffers + cp.async staging.
//  k1/k2 (projections): 3-term split  Ah*Bh + Al*Bh + Ah*Bl  (~1e-5 error)
//  k3 (fused bilinear): 2-term split  Ah*Bh + Al*Bh = A @ fp16(Wp)^T
//     -> only error is fp16 rounding of Wp (~2.8e-4), B-lo never loaded.
//
// Fragment-permuted layouts (mma.m16n8k16.row.col):
//  A word idx: ((k16*(ROWS/16)+m16)*32+lane)*4+s, s in 0..3:
//    half2{ X[m16*16+(s&1)*8+g][k16*16+(s>>1)*8+2t], X[..+1] }, g=lane>>2, t=lane&3
//  B word idx: ((k16*(NROWS/8)+n8)*32+lane)*2+s, s in 0..1:
//    half2{ X[n8*8+g][k16*16+s*8+2t], X[..+1] }

namespace {

constexpr int Bsz = 32, Mq = 32, Rr = 128;
constexpr int DL = 1024, DR = 2048, DK = 256, DF = 256;

// ---- global scratch (device-code references only) ----
__device__ float g_up[Bsz * Mq * DK];
__device__ float g_vp[Bsz * Rr * DK];
__device__ uint32_t uA_h[DL * Bsz * Mq / 2],  uA_l[DL * Bsz * Mq / 2];
__device__ uint32_t vA_h[(size_t)Bsz * Rr * DR / 2], vA_l[(size_t)Bsz * Rr * DR / 2];
__device__ uint32_t WuB_h[DK * DL / 2], WuB_l[DK * DL / 2];
__device__ uint32_t WvB_h[DK * DR / 2], WvB_l[DK * DR / 2];
__device__ uint32_t WpB_h[DF * DK / 2], WpB_l[DF * DK / 2];   // _l unused by k3 now

__device__ __forceinline__ void mma_fp16(float* c, const uint32_t* a, const uint32_t* b) {
    asm volatile(
        "mma.sync.aligned.m16n8k16.row.col.f32.f16.f16.f32 "
        "{%0,%1,%2,%3}, {%4,%5,%6,%7}, {%8,%9}, {%0,%1,%2,%3};"
        : "+f"(c[0]), "+f"(c[1]), "+f"(c[2]), "+f"(c[3])
        : "r"(a[0]), "r"(a[1]), "r"(a[2]), "r"(a[3]), "r"(b[0]), "r"(b[1]));
}

__device__ __forceinline__ void split2(float x, __half& hi, __half& lo) {
    hi = __float2half_rn(x);
    lo = __float2half_rn(x - __half2float(hi));
}
__device__ __forceinline__ uint32_t pack2(__half a, __half b) {
    return (uint32_t)__half_as_ushort(a) | ((uint32_t)__half_as_ushort(b) << 16);
}
__device__ __forceinline__ void split_pack2(float x0, float x1, uint32_t& h, uint32_t& l) {
    __half h0, l0, h1, l1;
    split2(x0, h0, l0); split2(x1, h1, l1);
    h = pack2(h0, h1); l = pack2(l0, l1);
}

__device__ __forceinline__ void cp16(void* sdst, const void* gsrc) {
    uint32_t sa = (uint32_t)__cvta_generic_to_shared(sdst);
    asm volatile("cp.async.cg.shared.global [%0], [%1], 16;" :: "r"(sa), "l"(gsrc) : "memory");
}
#define CP_COMMIT() asm volatile("cp.async.commit_group;" ::: "memory")
#define CP_WAIT0()  asm volatile("cp.async.wait_group 0;"  ::: "memory")

// ---- prep: fp32 row-major -> permuted hi/lo fp16 frag buffers ----
__device__ __forceinline__ void prep_A_body(
    const float* __restrict__ X, uint32_t* __restrict__ H,
    uint32_t* __restrict__ L, int ROWS16, int K)
{
    const int t = blockIdx.x * blockDim.x + threadIdx.x;
    const int lane = t & 31, fb = t >> 5;
    const int m16 = fb % ROWS16, k16 = fb / ROWS16;
    const int g = lane >> 2, tt = lane & 3;
    uint32_t h[4], l[4];
    #pragma unroll
    for (int s = 0; s < 4; s++) {
        const int row = m16 * 16 + (s & 1) * 8 + g;
        const int kk  = k16 * 16 + (s >> 1) * 8 + 2 * tt;
        const float2 x = *(const float2*)&X[(size_t)row * K + kk];
        split_pack2(x.x, x.y, h[s], l[s]);
    }
    const size_t o = (size_t)(fb * 32 + lane) * 4;
    *(uint4*)&H[o] = make_uint4(h[0], h[1], h[2], h[3]);
    *(uint4*)&L[o] = make_uint4(l[0], l[1], l[2], l[3]);
}

__device__ __forceinline__ void prep_B_body(
    const float* __restrict__ X, uint32_t* __restrict__ H,
    uint32_t* __restrict__ L, int NROWS8, int K)
{
    const int t = blockIdx.x * blockDim.x + threadIdx.x;
    const int lane = t & 31, fb = t >> 5;
    const int n8 = fb % NROWS8, k16 = fb / NROWS8;
    const int g = lane >> 2, tt = lane & 3;
    uint32_t h[2], l[2];
    #pragma unroll
    for (int s = 0; s < 2; s++) {
        const int row = n8 * 8 + g;
        const int kk  = k16 * 16 + s * 8 + 2 * tt;
        const float2 x = *(const float2*)&X[(size_t)row * K + kk];
        split_pack2(x.x, x.y, h[s], l[s]);
    }
    const size_t o = (size_t)(fb * 32 + lane) * 2;
    *(uint2*)&H[o] = make_uint2(h[0], h[1]);
    *(uint2*)&L[o] = make_uint2(l[0], l[1]);
}

__global__ void prep_u (const float* __restrict__ X) { prep_A_body(X, uA_h, uA_l, 64,  DL); }
__global__ void prep_v (const float* __restrict__ X) { prep_A_body(X, vA_h, vA_l, 256, DR); }
__global__ void prep_wu(const float* __restrict__ X) { prep_B_body(X, WuB_h, WuB_l, 32, DL); }
__global__ void prep_wv(const float* __restrict__ X) { prep_B_body(X, WvB_h, WvB_l, 32, DR); }
__global__ void prep_wp(const float* __restrict__ X) { prep_B_body(X, WpB_h, WpB_l, 32, DK); }

// ---- GEMM core ----
// B_LO: include the Ah*Bl term (3-term split) and stage Bl; else 2-term.
template <int TM, int TN, int WM, int WN, int KDIM, int AROWS, int NROWS,
          bool A_COPY, bool RELU, bool B_LO>
__device__ __forceinline__ void gemm_core(
    const uint32_t* __restrict__ Agh, const uint32_t* __restrict__ Agl,
    const float* __restrict__ Afp,
    const uint32_t* __restrict__ Bgh, const uint32_t* __restrict__ Bgl,
    const float* __restrict__ wvec, const float* __restrict__ bias,
    float* __restrict__ C, int m0, int n0)
{
    constexpr int THREADS = WM * WN * 32;
    constexpr int MT = TM / WM / 16;
    constexpr int NT = TN / WN / 8;
    constexpr int NC = KDIM / 32;
    constexpr int AW = TM * 16;            // words per A sub-buffer per chunk
    constexpr int BW = TN * 16;
    constexpr int M16 = TM / 16, N8 = TN / 8;
    constexpr int FJ = (TM * 32 / 4) / THREADS;
    constexpr int NB = B_LO ? 2 : 1;       // B sub-buffers

    extern __shared__ uint32_t smem[];
    float* ws = (float*)smem;              // [256]
    float* bs = (float*)(smem + 256);      // [256]
    constexpr int OFF = 512;
    constexpr int STAGE = 2 * AW + NB * BW;

    const int tid = threadIdx.x;
    const int wid = tid >> 5, lane = tid & 31;
    const int wm = wid % WM, wn = wid / WM;

    if (!A_COPY) { if (tid < 256) ws[tid] = wvec[tid]; }
    if (RELU)    { if (tid < TN)  bs[tid] = bias[n0 + tid]; }
    if (!A_COPY || RELU) __syncthreads();

    float c[MT][NT][4] = {};
    float4 ar[FJ];

    auto ldgA = [&](int ck) {
        const int kt = ck * 32;
        #pragma unroll
        for (int j = 0; j < FJ; j++) {
            const int i = j * THREADS + tid;
            const int row = i >> 3, c4 = i & 7;
            ar[j] = *(const float4*)&Afp[(size_t)row * KDIM + kt + c4 * 4];
        }
    };
    auto stsA = [&](int ck, int st) {
        uint32_t* sAh = smem + OFF + st * STAGE;
        uint32_t* sAl = sAh + AW;
        const int kt = ck * 32;
        #pragma unroll
        for (int j = 0; j < FJ; j++) {
            const int i = j * THREADS + tid;
            const int row = i >> 3, c4 = i & 7;
            float4 va = ar[j];
            const float4 w4 = *(const float4*)&ws[kt + c4 * 4];
            va.x *= w4.x; va.y *= w4.y; va.z *= w4.z; va.w *= w4.w;
            const int kc = c4 >> 2, reg = (c4 >> 1) & 1, lp = (c4 & 1) * 2;
            const int mt = row >> 4, r = row & 15, half = r >> 3, g = r & 7;
            const int a0 = ((kc * M16 + mt) * 32 + g * 4 + lp) * 4 + half + 2 * reg;
            uint32_t h0, l0, h1, l1;
            split_pack2(va.x, va.y, h0, l0);
            split_pack2(va.z, va.w, h1, l1);
            sAh[a0] = h0; sAh[a0 + 4] = h1;
            sAl[a0] = l0; sAl[a0 + 4] = l1;
        }
    };
    auto cpA = [&](int ck, int st) {
        uint32_t* sAh = smem + OFF + st * STAGE;
        uint32_t* sAl = sAh + AW;
        constexpr int AU4 = AW / (4 * THREADS);
        #pragma unroll
        for (int j = 0; j < AU4; j++) {
            const int w = (j * THREADS + tid) * 4;
            const int lb = w >> 7, off = w & 127;
            const int k16h = lb / M16, m16l = lb % M16;
            const size_t gw = ((size_t)(2 * ck + k16h) * (AROWS / 16) + m0 / 16 + m16l) * 128 + off;
            cp16(&sAh[w], &Agh[gw]);
            cp16(&sAl[w], &Agl[gw]);
        }
    };
    auto cpB = [&](int ck, int st) {
        uint32_t* sBh = smem + OFF + st * STAGE + 2 * AW;
        uint32_t* sBl = sBh + BW;
        constexpr int BU4 = BW / (4 * THREADS);
        #pragma unroll
        for (int j = 0; j < BU4; j++) {
            const int w = (j * THREADS + tid) * 4;
            const int lb = w >> 6, off = w & 63;
            const int k16h = lb / N8, n8l = lb % N8;
            const size_t gw = ((size_t)(2 * ck + k16h) * (NROWS / 8) + n0 / 8 + n8l) * 64 + off;
            cp16(&sBh[w], &Bgh[gw]);
            if (B_LO) cp16(&sBl[w], &Bgl[gw]);
        }
    };

    auto compute_chunk = [&](int st) {
        const uint32_t* sAh = smem + OFF + st * STAGE;
        const uint32_t* sAl = sAh + AW;
        const uint32_t* sBh = sAl + AW;
        const uint32_t* sBl = sBh + BW;
        #pragma unroll
        for (int kc = 0; kc < 2; kc++) {
            uint32_t ah[MT][4], al[MT][4];
            #pragma unroll
            for (int mt = 0; mt < MT; mt++) {
                const int base = ((kc * M16 + wm * MT + mt) * 32 + lane) * 4;
                const uint4 vh = *(const uint4*)&sAh[base];
                ah[mt][0] = vh.x; ah[mt][1] = vh.y; ah[mt][2] = vh.z; ah[mt][3] = vh.w;
                const uint4 vl = *(const uint4*)&sAl[base];
                al[mt][0] = vl.x; al[mt][1] = vl.y; al[mt][2] = vl.z; al[mt][3] = vl.w;
            }
            uint32_t bh[2][2], bl[2][2];
            {
                const int base = ((kc * N8 + wn * NT) * 32 + lane) * 2;
                const uint2 vh = *(const uint2*)&sBh[base]; bh[0][0] = vh.x; bh[0][1] = vh.y;
                if (B_LO) { const uint2 vl = *(const uint2*)&sBl[base]; bl[0][0] = vl.x; bl[0][1] = vl.y; }
            }
            #pragma unroll
            for (int j = 0; j < NT; j++) {
                const int cur = j & 1, nxt = cur ^ 1;
                if (j + 1 < NT) {
                    const int base = ((kc * N8 + wn * NT + j + 1) * 32 + lane) * 2;
                    const uint2 vh = *(const uint2*)&sBh[base]; bh[nxt][0] = vh.x; bh[nxt][1] = vh.y;
                    if (B_LO) { const uint2 vl = *(const uint2*)&sBl[base]; bl[nxt][0] = vl.x; bl[nxt][1] = vl.y; }
                }
                #pragma unroll
                for (int mt = 0; mt < MT; mt++) {
                    mma_fp16(c[mt][j], ah[mt], bh[cur]);
                    mma_fp16(c[mt][j], al[mt], bh[cur]);
                    if (B_LO) mma_fp16(c[mt][j], ah[mt], bl[cur]);
                }
            }
        }
    };

    // prologue
    if (A_COPY) cpA(0, 0); else ldgA(0);
    cpB(0, 0); CP_COMMIT();
    if (!A_COPY) stsA(0, 0);
    CP_WAIT0();
    __syncthreads();

    for (int ck = 0; ck < NC; ck++) {
        const int par = ck & 1;
        if (ck + 1 < NC) {
            if (A_COPY) cpA(ck + 1, par ^ 1); else ldgA(ck + 1);
            cpB(ck + 1, par ^ 1);
            CP_COMMIT();
        }
        compute_chunk(par);
        if (ck + 1 < NC && !A_COPY) stsA(ck + 1, par ^ 1);
        CP_WAIT0();
        __syncthreads();
    }

    const int g = lane >> 2, t = lane & 3;
    #pragma unroll
    for (int mt = 0; mt < MT; mt++) {
        const int row0 = wm * MT * 16 + mt * 16 + g;
        #pragma unroll
        for (int j = 0; j < NT; j++) {
            const int col = wn * NT * 8 + j * 8 + t * 2;
            float2 v0 = make_float2(c[mt][j][0], c[mt][j][1]);
            float2 v1 = make_float2(c[mt][j][2], c[mt][j][3]);
            if (RELU) {
                const float b0 = bs[col], b1 = bs[col + 1];
                v0.x = fmaxf(v0.x + b0, 0.0f); v0.y = fmaxf(v0.y + b1, 0.0f);
                v1.x = fmaxf(v1.x + b0, 0.0f); v1.y = fmaxf(v1.y + b1, 0.0f);
            }
            *(float2*)&C[(size_t)(m0 + row0) * 256 + n0 + col]     = v0;
            *(float2*)&C[(size_t)(m0 + row0 + 8) * 256 + n0 + col] = v1;
        }
    }
}

// k1: up[1024,256] = u @ Wu^T. 64x32 tiles, 128 thr, grid (8,16). 3-term.
__global__ __launch_bounds__(128, 4) void k1_up() {
    gemm_core<64, 32, 2, 2, DL, 1024, DK, true, false, true>(
        uA_h, uA_l, nullptr, WuB_h, WuB_l, nullptr, nullptr,
        g_up, blockIdx.y * 64, blockIdx.x * 32);
}

// k2: vp[4096,256] = v @ Wv^T. 64x64 tiles, 128 thr, grid (4,64). 3-term.
__global__ __launch_bounds__(128, 4) void k2_vp() {
    gemm_core<64, 64, 2, 2, DR, Bsz * Rr, DK, true, false, true>(
        vA_h, vA_l, nullptr, WvB_h, WvB_l, nullptr, nullptr,
        g_vp, blockIdx.y * 64, blockIdx.x * 64);
}

// k3: out = relu((vp[b]*diag(up[bm])) @ fp16(Wp)^T + bp). 128x256, 512 thr. 2-term.
__global__ __launch_bounds__(512, 1) void k3_fuse(const float* __restrict__ bp,
                                                  float* __restrict__ out) {
    const int bm = blockIdx.x, b = bm >> 5;
    gemm_core<128, 256, 4, 4, DK, Rr, DF, false, true, false>(
        nullptr, nullptr, g_vp + (size_t)b * Rr * DK,
        WpB_h, WpB_l, g_up + (size_t)bm * DK, bp,
        out + (size_t)bm * Rr * DF, 0, 0);
}

constexpr int SMEM_K1 = (512 + 2 * (2 * 64 * 16 + 2 * 32 * 16)) * 4;    // 26624
constexpr int SMEM_K2 = (512 + 2 * (2 * 64 * 16 + 2 * 64 * 16)) * 4;    // 34816
constexpr int SMEM_K3 = (512 + 2 * (2 * 128 * 16 + 1 * 256 * 16)) * 4;  // 67584

} // namespace

extern "C" void kernel_launch(void* const* d_in, const int* in_sizes, int n_in,
                              void* d_out, int out_size)
{
    (void)in_sizes; (void)n_in; (void)out_size;
    const float* u  = (const float*)d_in[0];   // (32, 32, 1024)
    const float* v  = (const float*)d_in[1];   // (32, 128, 2048)
    const float* Wu = (const float*)d_in[2];   // (256, 1024)
    const float* Wv = (const float*)d_in[3];   // (256, 2048)
    const float* Wp = (const float*)d_in[4];   // (256, 256)
    const float* bp = (const float*)d_in[5];   // (256,)
    float* out = (float*)d_out;                // (32, 32, 128, 256)

    cudaFuncSetAttribute(k1_up,   cudaFuncAttributeMaxDynamicSharedMemorySize, SMEM_K1);
    cudaFuncSetAttribute(k2_vp,   cudaFuncAttributeMaxDynamicSharedMemorySize, SMEM_K2);
    cudaFuncSetAttribute(k3_fuse, cudaFuncAttributeMaxDynamicSharedMemorySize, SMEM_K3);

    prep_u <<<(64 * 64 * 32)   / 256, 256>>>(u);
    prep_v <<<(256 * 128 * 32) / 256, 256>>>(v);
    prep_wu<<<(32 * 64 * 32)   / 256, 256>>>(Wu);
    prep_wv<<<(32 * 128 * 32)  / 256, 256>>>(Wv);
    prep_wp<<<(32 * 16 * 32)   / 256, 256>>>(Wp);

    k1_up<<<dim3(8, 16), 128, SMEM_K1>>>();           // 128 CTAs
    k2_vp<<<dim3(4, 64), 128, SMEM_K2>>>();           // 256 CTAs
    k3_fuse<<<1024, 512, SMEM_K3>>>(bp, out);         // 1024 CTAs
}

// round 11
// speedup vs baseline: 4.1960x; 1.2092x over previous
#include <cuda_runtime.h>
#include <cuda_fp16.h>
#include <cstdint>

// LowRankBilinearFusion via fp16-split mma.sync with pre-permuted global
// fragment buffers + cp.async staging.
//  k1/k2 (projections): 3-term split  Ah*Bh + Al*Bh + Ah*Bl  (~1e-5 error)
//  k3 (fused bilinear): 1-term pure fp16  Ah*Bh
//     -> error = fp16 rounding of A and Wp (~3e-4 combined), fp32 accum.
//
// Fragment-permuted layouts (mma.m16n8k16.row.col):
//  A word idx: ((k16*(ROWS/16)+m16)*32+lane)*4+s, s in 0..3:
//    half2{ X[m16*16+(s&1)*8+g][k16*16+(s>>1)*8+2t], X[..+1] }, g=lane>>2, t=lane&3
//  B word idx: ((k16*(NROWS/8)+n8)*32+lane)*2+s, s in 0..1:
//    half2{ X[n8*8+g][k16*16+s*8+2t], X[..+1] }

namespace {

constexpr int Bsz = 32, Mq = 32, Rr = 128;
constexpr int DL = 1024, DR = 2048, DK = 256, DF = 256;

// ---- global scratch (device-code references only) ----
__device__ float g_up[Bsz * Mq * DK];
__device__ float g_vp[Bsz * Rr * DK];
__device__ uint32_t uA_h[DL * Bsz * Mq / 2],  uA_l[DL * Bsz * Mq / 2];
__device__ uint32_t vA_h[(size_t)Bsz * Rr * DR / 2], vA_l[(size_t)Bsz * Rr * DR / 2];
__device__ uint32_t WuB_h[DK * DL / 2], WuB_l[DK * DL / 2];
__device__ uint32_t WvB_h[DK * DR / 2], WvB_l[DK * DR / 2];
__device__ uint32_t WpB_h[DF * DK / 2], WpB_l[DF * DK / 2];   // _l unused by k3

__device__ __forceinline__ void mma_fp16(float* c, const uint32_t* a, const uint32_t* b) {
    asm volatile(
        "mma.sync.aligned.m16n8k16.row.col.f32.f16.f16.f32 "
        "{%0,%1,%2,%3}, {%4,%5,%6,%7}, {%8,%9}, {%0,%1,%2,%3};"
        : "+f"(c[0]), "+f"(c[1]), "+f"(c[2]), "+f"(c[3])
        : "r"(a[0]), "r"(a[1]), "r"(a[2]), "r"(a[3]), "r"(b[0]), "r"(b[1]));
}

__device__ __forceinline__ void split2(float x, __half& hi, __half& lo) {
    hi = __float2half_rn(x);
    lo = __float2half_rn(x - __half2float(hi));
}
__device__ __forceinline__ uint32_t pack2(__half a, __half b) {
    return (uint32_t)__half_as_ushort(a) | ((uint32_t)__half_as_ushort(b) << 16);
}
__device__ __forceinline__ void split_pack2(float x0, float x1, uint32_t& h, uint32_t& l) {
    __half h0, l0, h1, l1;
    split2(x0, h0, l0); split2(x1, h1, l1);
    h = pack2(h0, h1); l = pack2(l0, l1);
}
__device__ __forceinline__ uint32_t pack_hi2(float x0, float x1) {
    return pack2(__float2half_rn(x0), __float2half_rn(x1));
}

__device__ __forceinline__ void cp16(void* sdst, const void* gsrc) {
    uint32_t sa = (uint32_t)__cvta_generic_to_shared(sdst);
    asm volatile("cp.async.cg.shared.global [%0], [%1], 16;" :: "r"(sa), "l"(gsrc) : "memory");
}
#define CP_COMMIT() asm volatile("cp.async.commit_group;" ::: "memory")
#define CP_WAIT0()  asm volatile("cp.async.wait_group 0;"  ::: "memory")

// ---- prep: fp32 row-major -> permuted hi/lo fp16 frag buffers ----
__device__ __forceinline__ void prep_A_body(
    const float* __restrict__ X, uint32_t* __restrict__ H,
    uint32_t* __restrict__ L, int ROWS16, int K)
{
    const int t = blockIdx.x * blockDim.x + threadIdx.x;
    const int lane = t & 31, fb = t >> 5;
    const int m16 = fb % ROWS16, k16 = fb / ROWS16;
    const int g = lane >> 2, tt = lane & 3;
    uint32_t h[4], l[4];
    #pragma unroll
    for (int s = 0; s < 4; s++) {
        const int row = m16 * 16 + (s & 1) * 8 + g;
        const int kk  = k16 * 16 + (s >> 1) * 8 + 2 * tt;
        const float2 x = *(const float2*)&X[(size_t)row * K + kk];
        split_pack2(x.x, x.y, h[s], l[s]);
    }
    const size_t o = (size_t)(fb * 32 + lane) * 4;
    *(uint4*)&H[o] = make_uint4(h[0], h[1], h[2], h[3]);
    *(uint4*)&L[o] = make_uint4(l[0], l[1], l[2], l[3]);
}

__device__ __forceinline__ void prep_B_body(
    const float* __restrict__ X, uint32_t* __restrict__ H,
    uint32_t* __restrict__ L, int NROWS8, int K)
{
    const int t = blockIdx.x * blockDim.x + threadIdx.x;
    const int lane = t & 31, fb = t >> 5;
    const int n8 = fb % NROWS8, k16 = fb / NROWS8;
    const int g = lane >> 2, tt = lane & 3;
    uint32_t h[2], l[2];
    #pragma unroll
    for (int s = 0; s < 2; s++) {
        const int row = n8 * 8 + g;
        const int kk  = k16 * 16 + s * 8 + 2 * tt;
        const float2 x = *(const float2*)&X[(size_t)row * K + kk];
        split_pack2(x.x, x.y, h[s], l[s]);
    }
    const size_t o = (size_t)(fb * 32 + lane) * 2;
    *(uint2*)&H[o] = make_uint2(h[0], h[1]);
    *(uint2*)&L[o] = make_uint2(l[0], l[1]);
}

__global__ void prep_u (const float* __restrict__ X) { prep_A_body(X, uA_h, uA_l, 64,  DL); }
__global__ void prep_v (const float* __restrict__ X) { prep_A_body(X, vA_h, vA_l, 256, DR); }
__global__ void prep_wu(const float* __restrict__ X) { prep_B_body(X, WuB_h, WuB_l, 32, DL); }
__global__ void prep_wv(const float* __restrict__ X) { prep_B_body(X, WvB_h, WvB_l, 32, DR); }
__global__ void prep_wp(const float* __restrict__ X) { prep_B_body(X, WpB_h, WpB_l, 32, DK); }

// ---- GEMM core ----
// A_LO/B_LO: include lo-side split terms (and stage the lo buffers).
template <int TM, int TN, int WM, int WN, int KDIM, int AROWS, int NROWS,
          bool A_COPY, bool RELU, bool A_LO, bool B_LO>
__device__ __forceinline__ void gemm_core(
    const uint32_t* __restrict__ Agh, const uint32_t* __restrict__ Agl,
    const float* __restrict__ Afp,
    const uint32_t* __restrict__ Bgh, const uint32_t* __restrict__ Bgl,
    const float* __restrict__ wvec, const float* __restrict__ bias,
    float* __restrict__ C, int m0, int n0)
{
    constexpr int THREADS = WM * WN * 32;
    constexpr int MT = TM / WM / 16;
    constexpr int NT = TN / WN / 8;
    constexpr int NC = KDIM / 32;
    constexpr int AW = TM * 16;            // words per A sub-buffer per chunk
    constexpr int BW = TN * 16;
    constexpr int M16 = TM / 16, N8 = TN / 8;
    constexpr int FJ = (TM * 32 / 4) / THREADS;
    constexpr int NA = A_LO ? 2 : 1;
    constexpr int NB = B_LO ? 2 : 1;

    extern __shared__ uint32_t smem[];
    float* ws = (float*)smem;              // [256]
    float* bs = (float*)(smem + 256);      // [256]
    constexpr int OFF = 512;
    constexpr int STAGE = NA * AW + NB * BW;

    const int tid = threadIdx.x;
    const int wid = tid >> 5, lane = tid & 31;
    const int wm = wid % WM, wn = wid / WM;

    if (!A_COPY) { if (tid < 256) ws[tid] = wvec[tid]; }
    if (RELU)    { if (tid < TN)  bs[tid] = bias[n0 + tid]; }
    if (!A_COPY || RELU) __syncthreads();

    float c[MT][NT][4] = {};
    float4 ar[FJ];

    auto ldgA = [&](int ck) {
        const int kt = ck * 32;
        #pragma unroll
        for (int j = 0; j < FJ; j++) {
            const int i = j * THREADS + tid;
            const int row = i >> 3, c4 = i & 7;
            ar[j] = *(const float4*)&Afp[(size_t)row * KDIM + kt + c4 * 4];
        }
    };
    auto stsA = [&](int ck, int st) {
        uint32_t* sAh = smem + OFF + st * STAGE;
        uint32_t* sAl = sAh + AW;
        const int kt = ck * 32;
        #pragma unroll
        for (int j = 0; j < FJ; j++) {
            const int i = j * THREADS + tid;
            const int row = i >> 3, c4 = i & 7;
            float4 va = ar[j];
            const float4 w4 = *(const float4*)&ws[kt + c4 * 4];
            va.x *= w4.x; va.y *= w4.y; va.z *= w4.z; va.w *= w4.w;
            const int kc = c4 >> 2, reg = (c4 >> 1) & 1, lp = (c4 & 1) * 2;
            const int mt = row >> 4, r = row & 15, half = r >> 3, g = r & 7;
            const int a0 = ((kc * M16 + mt) * 32 + g * 4 + lp) * 4 + half + 2 * reg;
            if (A_LO) {
                uint32_t h0, l0, h1, l1;
                split_pack2(va.x, va.y, h0, l0);
                split_pack2(va.z, va.w, h1, l1);
                sAh[a0] = h0; sAh[a0 + 4] = h1;
                sAl[a0] = l0; sAl[a0 + 4] = l1;
            } else {
                sAh[a0]     = pack_hi2(va.x, va.y);
                sAh[a0 + 4] = pack_hi2(va.z, va.w);
            }
        }
    };
    auto cpA = [&](int ck, int st) {
        uint32_t* sAh = smem + OFF + st * STAGE;
        uint32_t* sAl = sAh + AW;
        constexpr int AU4 = AW / (4 * THREADS);
        #pragma unroll
        for (int j = 0; j < AU4; j++) {
            const int w = (j * THREADS + tid) * 4;
            const int lb = w >> 7, off = w & 127;
            const int k16h = lb / M16, m16l = lb % M16;
            const size_t gw = ((size_t)(2 * ck + k16h) * (AROWS / 16) + m0 / 16 + m16l) * 128 + off;
            cp16(&sAh[w], &Agh[gw]);
            if (A_LO) cp16(&sAl[w], &Agl[gw]);
        }
    };
    auto cpB = [&](int ck, int st) {
        uint32_t* sBh = smem + OFF + st * STAGE + NA * AW;
        uint32_t* sBl = sBh + BW;
        constexpr int BU4 = BW / (4 * THREADS);
        #pragma unroll
        for (int j = 0; j < BU4; j++) {
            const int w = (j * THREADS + tid) * 4;
            const int lb = w >> 6, off = w & 63;
            const int k16h = lb / N8, n8l = lb % N8;
            const size_t gw = ((size_t)(2 * ck + k16h) * (NROWS / 8) + n0 / 8 + n8l) * 64 + off;
            cp16(&sBh[w], &Bgh[gw]);
            if (B_LO) cp16(&sBl[w], &Bgl[gw]);
        }
    };

    auto compute_chunk = [&](int st) {
        const uint32_t* sAh = smem + OFF + st * STAGE;
        const uint32_t* sAl = sAh + AW;
        const uint32_t* sBh = smem + OFF + st * STAGE + NA * AW;
        const uint32_t* sBl = sBh + BW;
        #pragma unroll
        for (int kc = 0; kc < 2; kc++) {
            uint32_t ah[MT][4], al[MT][4];
            #pragma unroll
            for (int mt = 0; mt < MT; mt++) {
                const int base = ((kc * M16 + wm * MT + mt) * 32 + lane) * 4;
                const uint4 vh = *(const uint4*)&sAh[base];
                ah[mt][0] = vh.x; ah[mt][1] = vh.y; ah[mt][2] = vh.z; ah[mt][3] = vh.w;
                if (A_LO) {
                    const uint4 vl = *(const uint4*)&sAl[base];
                    al[mt][0] = vl.x; al[mt][1] = vl.y; al[mt][2] = vl.z; al[mt][3] = vl.w;
                }
            }
            uint32_t bh[2][2], bl[2][2];
            {
                const int base = ((kc * N8 + wn * NT) * 32 + lane) * 2;
                const uint2 vh = *(const uint2*)&sBh[base]; bh[0][0] = vh.x; bh[0][1] = vh.y;
                if (B_LO) { const uint2 vl = *(const uint2*)&sBl[base]; bl[0][0] = vl.x; bl[0][1] = vl.y; }
            }
            #pragma unroll
            for (int j = 0; j < NT; j++) {
                const int cur = j & 1, nxt = cur ^ 1;
                if (j + 1 < NT) {
                    const int base = ((kc * N8 + wn * NT + j + 1) * 32 + lane) * 2;
                    const uint2 vh = *(const uint2*)&sBh[base]; bh[nxt][0] = vh.x; bh[nxt][1] = vh.y;
                    if (B_LO) { const uint2 vl = *(const uint2*)&sBl[base]; bl[nxt][0] = vl.x; bl[nxt][1] = vl.y; }
                }
                #pragma unroll
                for (int mt = 0; mt < MT; mt++) {
                    mma_fp16(c[mt][j], ah[mt], bh[cur]);
                    if (A_LO) mma_fp16(c[mt][j], al[mt], bh[cur]);
                    if (B_LO) mma_fp16(c[mt][j], ah[mt], bl[cur]);
                }
            }
        }
    };

    // prologue
    if (A_COPY) cpA(0, 0); else ldgA(0);
    cpB(0, 0); CP_COMMIT();
    if (!A_COPY) stsA(0, 0);
    CP_WAIT0();
    __syncthreads();

    for (int ck = 0; ck < NC; ck++) {
        const int par = ck & 1;
        if (ck + 1 < NC) {
            if (A_COPY) cpA(ck + 1, par ^ 1); else ldgA(ck + 1);
            cpB(ck + 1, par ^ 1);
            CP_COMMIT();
        }
        compute_chunk(par);
        if (ck + 1 < NC && !A_COPY) stsA(ck + 1, par ^ 1);
        CP_WAIT0();
        __syncthreads();
    }

    const int g = lane >> 2, t = lane & 3;
    #pragma unroll
    for (int mt = 0; mt < MT; mt++) {
        const int row0 = wm * MT * 16 + mt * 16 + g;
        #pragma unroll
        for (int j = 0; j < NT; j++) {
            const int col = wn * NT * 8 + j * 8 + t * 2;
            float2 v0 = make_float2(c[mt][j][0], c[mt][j][1]);
            float2 v1 = make_float2(c[mt][j][2], c[mt][j][3]);
            if (RELU) {
                const float b0 = bs[col], b1 = bs[col + 1];
                v0.x = fmaxf(v0.x + b0, 0.0f); v0.y = fmaxf(v0.y + b1, 0.0f);
                v1.x = fmaxf(v1.x + b0, 0.0f); v1.y = fmaxf(v1.y + b1, 0.0f);
            }
            *(float2*)&C[(size_t)(m0 + row0) * 256 + n0 + col]     = v0;
            *(float2*)&C[(size_t)(m0 + row0 + 8) * 256 + n0 + col] = v1;
        }
    }
}

// k1: up[1024,256] = u @ Wu^T. 64x32 tiles, 128 thr, grid (8,16). 3-term.
__global__ __launch_bounds__(128, 4) void k1_up() {
    gemm_core<64, 32, 2, 2, DL, 1024, DK, true, false, true, true>(
        uA_h, uA_l, nullptr, WuB_h, WuB_l, nullptr, nullptr,
        g_up, blockIdx.y * 64, blockIdx.x * 32);
}

// k2: vp[4096,256] = v @ Wv^T. 64x64 tiles, 128 thr, grid (4,64). 3-term.
__global__ __launch_bounds__(128, 4) void k2_vp() {
    gemm_core<64, 64, 2, 2, DR, Bsz * Rr, DK, true, false, true, true>(
        vA_h, vA_l, nullptr, WvB_h, WvB_l, nullptr, nullptr,
        g_vp, blockIdx.y * 64, blockIdx.x * 64);
}

// k3: out = relu(fp16(vp[b]*diag(up[bm])) @ fp16(Wp)^T + bp). Pure fp16, fp32 accum.
__global__ __launch_bounds__(512, 1) void k3_fuse(const float* __restrict__ bp,
                                                  float* __restrict__ out) {
    const int bm = blockIdx.x, b = bm >> 5;
    gemm_core<128, 256, 4, 4, DK, Rr, DF, false, true, false, false>(
        nullptr, nullptr, g_vp + (size_t)b * Rr * DK,
        WpB_h, WpB_l, g_up + (size_t)bm * DK, bp,
        out + (size_t)bm * Rr * DF, 0, 0);
}

constexpr int SMEM_K1 = (512 + 2 * (2 * 64 * 16 + 2 * 32 * 16)) * 4;    // 26624
constexpr int SMEM_K2 = (512 + 2 * (2 * 64 * 16 + 2 * 64 * 16)) * 4;    // 34816
constexpr int SMEM_K3 = (512 + 2 * (1 * 128 * 16 + 1 * 256 * 16)) * 4;  // 51200

} // namespace

extern "C" void kernel_launch(void* const* d_in, const int* in_sizes, int n_in,
                              void* d_out, int out_size)
{
    (void)in_sizes; (void)n_in; (void)out_size;
    const float* u  = (const float*)d_in[0];   // (32, 32, 1024)
    const float* v  = (const float*)d_in[1];   // (32, 128, 2048)
    const float* Wu = (const float*)d_in[2];   // (256, 1024)
    const float* Wv = (const float*)d_in[3];   // (256, 2048)
    const float* Wp = (const float*)d_in[4];   // (256, 256)
    const float* bp = (const float*)d_in[5];   // (256,)
    float* out = (float*)d_out;                // (32, 32, 128, 256)

    cudaFuncSetAttribute(k1_up,   cudaFuncAttributeMaxDynamicSharedMemorySize, SMEM_K1);
    cudaFuncSetAttribute(k2_vp,   cudaFuncAttributeMaxDynamicSharedMemorySize, SMEM_K2);
    cudaFuncSetAttribute(k3_fuse, cudaFuncAttributeMaxDynamicSharedMemorySize, SMEM_K3);

    prep_u <<<(64 * 64 * 32)   / 256, 256>>>(u);
    prep_v <<<(256 * 128 * 32) / 256, 256>>>(v);
    prep_wu<<<(32 * 64 * 32)   / 256, 256>>>(Wu);
    prep_wv<<<(32 * 128 * 32)  / 256, 256>>>(Wv);
    prep_wp<<<(32 * 16 * 32)   / 256, 256>>>(Wp);

    k1_up<<<dim3(8, 16), 128, SMEM_K1>>>();           // 128 CTAs
    k2_vp<<<dim3(4, 64), 128, SMEM_K2>>>();           // 256 CTAs
    k3_fuse<<<1024, 512, SMEM_K3>>>(bp, out);         // 1024 CTAs
}

// round 12
// speedup vs baseline: 4.6950x; 1.1189x over previous
#include <cuda_runtime.h>
#include <cuda_fp16.h>
#include <cstdint>

// LowRankBilinearFusion, fp16 mma.sync.
//  k1/k2 (projections): 3-term fp16 split (near-fp32)
//  k2 emits vp directly as pre-permuted fp16 A-fragments (vpA_h).
//  k3: pure fp16, all-cp.async; A = hmul2(vp_h, up_h) scaled in registers.

namespace {

constexpr int Bsz = 32, Mq = 32, Rr = 128;
constexpr int DL = 1024, DR = 2048, DK = 256, DF = 256;

// ---- global scratch (device-code references only) ----
__device__ float g_up[Bsz * Mq * DK];                               // fp32 up
__device__ uint32_t vpA_h[(size_t)Bsz * Rr * DK / 2];               // vp as fp16 A-frags (rows16=256)
__device__ uint32_t uA_h[DL * Bsz * Mq / 2],  uA_l[DL * Bsz * Mq / 2];
__device__ uint32_t vA_h[(size_t)Bsz * Rr * DR / 2], vA_l[(size_t)Bsz * Rr * DR / 2];
__device__ uint32_t WuB_h[DK * DL / 2], WuB_l[DK * DL / 2];
__device__ uint32_t WvB_h[DK * DR / 2], WvB_l[DK * DR / 2];
__device__ uint32_t WpB_h[DF * DK / 2], WpB_l[DF * DK / 2];

__device__ __forceinline__ void mma_fp16(float* c, const uint32_t* a, const uint32_t* b) {
    asm volatile(
        "mma.sync.aligned.m16n8k16.row.col.f32.f16.f16.f32 "
        "{%0,%1,%2,%3}, {%4,%5,%6,%7}, {%8,%9}, {%0,%1,%2,%3};"
        : "+f"(c[0]), "+f"(c[1]), "+f"(c[2]), "+f"(c[3])
        : "r"(a[0]), "r"(a[1]), "r"(a[2]), "r"(a[3]), "r"(b[0]), "r"(b[1]));
}

__device__ __forceinline__ void split2(float x, __half& hi, __half& lo) {
    hi = __float2half_rn(x);
    lo = __float2half_rn(x - __half2float(hi));
}
__device__ __forceinline__ uint32_t pack2(__half a, __half b) {
    return (uint32_t)__half_as_ushort(a) | ((uint32_t)__half_as_ushort(b) << 16);
}
__device__ __forceinline__ void split_pack2(float x0, float x1, uint32_t& h, uint32_t& l) {
    __half h0, l0, h1, l1;
    split2(x0, h0, l0); split2(x1, h1, l1);
    h = pack2(h0, h1); l = pack2(l0, l1);
}
__device__ __forceinline__ uint32_t pack_hi2(float x0, float x1) {
    return pack2(__float2half_rn(x0), __float2half_rn(x1));
}
__device__ __forceinline__ uint32_t hmul2u(uint32_t a, uint32_t b) {
    __half2 r = __hmul2(*(__half2*)&a, *(__half2*)&b);
    return *(uint32_t*)&r;
}

__device__ __forceinline__ void cp16(void* sdst, const void* gsrc) {
    uint32_t sa = (uint32_t)__cvta_generic_to_shared(sdst);
    asm volatile("cp.async.cg.shared.global [%0], [%1], 16;" :: "r"(sa), "l"(gsrc) : "memory");
}
#define CP_COMMIT() asm volatile("cp.async.commit_group;" ::: "memory")
#define CP_WAIT0()  asm volatile("cp.async.wait_group 0;"  ::: "memory")

// ---- prep: fp32 row-major -> permuted hi/lo fp16 frag buffers ----
__device__ __forceinline__ void prep_A_body(
    const float* __restrict__ X, uint32_t* __restrict__ H,
    uint32_t* __restrict__ L, int ROWS16, int K)
{
    const int t = blockIdx.x * blockDim.x + threadIdx.x;
    const int lane = t & 31, fb = t >> 5;
    const int m16 = fb % ROWS16, k16 = fb / ROWS16;
    const int g = lane >> 2, tt = lane & 3;
    uint32_t h[4], l[4];
    #pragma unroll
    for (int s = 0; s < 4; s++) {
        const int row = m16 * 16 + (s & 1) * 8 + g;
        const int kk  = k16 * 16 + (s >> 1) * 8 + 2 * tt;
        const float2 x = *(const float2*)&X[(size_t)row * K + kk];
        split_pack2(x.x, x.y, h[s], l[s]);
    }
    const size_t o = (size_t)(fb * 32 + lane) * 4;
    *(uint4*)&H[o] = make_uint4(h[0], h[1], h[2], h[3]);
    *(uint4*)&L[o] = make_uint4(l[0], l[1], l[2], l[3]);
}

__device__ __forceinline__ void prep_B_body(
    const float* __restrict__ X, uint32_t* __restrict__ H,
    uint32_t* __restrict__ L, int NROWS8, int K)
{
    const int t = blockIdx.x * blockDim.x + threadIdx.x;
    const int lane = t & 31, fb = t >> 5;
    const int n8 = fb % NROWS8, k16 = fb / NROWS8;
    const int g = lane >> 2, tt = lane & 3;
    uint32_t h[2], l[2];
    #pragma unroll
    for (int s = 0; s < 2; s++) {
        const int row = n8 * 8 + g;
        const int kk  = k16 * 16 + s * 8 + 2 * tt;
        const float2 x = *(const float2*)&X[(size_t)row * K + kk];
        split_pack2(x.x, x.y, h[s], l[s]);
    }
    const size_t o = (size_t)(fb * 32 + lane) * 2;
    *(uint2*)&H[o] = make_uint2(h[0], h[1]);
    *(uint2*)&L[o] = make_uint2(l[0], l[1]);
}

__global__ void prep_u (const float* __restrict__ X) { prep_A_body(X, uA_h, uA_l, 64,  DL); }
__global__ void prep_v (const float* __restrict__ X) { prep_A_body(X, vA_h, vA_l, 256, DR); }
__global__ void prep_wu(const float* __restrict__ X) { prep_B_body(X, WuB_h, WuB_l, 32, DL); }
__global__ void prep_wv(const float* __restrict__ X) { prep_B_body(X, WvB_h, WvB_l, 32, DR); }
__global__ void prep_wp(const float* __restrict__ X) { prep_B_body(X, WpB_h, WpB_l, 32, DK); }

// ---- GEMM core for k1/k2 (3-term split, A from pre-permuted frags) ----
// HALF_OUT: write C as pre-permuted fp16 A-frag buffer (OUT_R16 = out rows/16).
template <int TM, int TN, int WM, int WN, int KDIM, int AROWS, int NROWS,
          bool HALF_OUT, int OUT_R16>
__device__ __forceinline__ void gemm_core(
    const uint32_t* __restrict__ Agh, const uint32_t* __restrict__ Agl,
    const uint32_t* __restrict__ Bgh, const uint32_t* __restrict__ Bgl,
    float* __restrict__ C, uint32_t* __restrict__ Cf, int m0, int n0)
{
    constexpr int THREADS = WM * WN * 32;
    constexpr int MT = TM / WM / 16;
    constexpr int NT = TN / WN / 8;
    constexpr int NC = KDIM / 32;
    constexpr int AW = TM * 16;
    constexpr int BW = TN * 16;
    constexpr int M16 = TM / 16, N8 = TN / 8;

    extern __shared__ uint32_t smem[];
    constexpr int OFF = 0;
    constexpr int STAGE = 2 * AW + 2 * BW;

    const int tid = threadIdx.x;
    const int wid = tid >> 5, lane = tid & 31;
    const int wm = wid % WM, wn = wid / WM;

    float c[MT][NT][4] = {};

    auto cpA = [&](int ck, int st) {
        uint32_t* sAh = smem + OFF + st * STAGE;
        uint32_t* sAl = sAh + AW;
        constexpr int AU4 = AW / (4 * THREADS);
        #pragma unroll
        for (int j = 0; j < AU4; j++) {
            const int w = (j * THREADS + tid) * 4;
            const int lb = w >> 7, off = w & 127;
            const int k16h = lb / M16, m16l = lb % M16;
            const size_t gw = ((size_t)(2 * ck + k16h) * (AROWS / 16) + m0 / 16 + m16l) * 128 + off;
            cp16(&sAh[w], &Agh[gw]);
            cp16(&sAl[w], &Agl[gw]);
        }
    };
    auto cpB = [&](int ck, int st) {
        uint32_t* sBh = smem + OFF + st * STAGE + 2 * AW;
        uint32_t* sBl = sBh + BW;
        constexpr int BU4 = BW / (4 * THREADS);
        #pragma unroll
        for (int j = 0; j < BU4; j++) {
            const int w = (j * THREADS + tid) * 4;
            const int lb = w >> 6, off = w & 63;
            const int k16h = lb / N8, n8l = lb % N8;
            const size_t gw = ((size_t)(2 * ck + k16h) * (NROWS / 8) + n0 / 8 + n8l) * 64 + off;
            cp16(&sBh[w], &Bgh[gw]);
            cp16(&sBl[w], &Bgl[gw]);
        }
    };

    auto compute_chunk = [&](int st) {
        const uint32_t* sAh = smem + OFF + st * STAGE;
        const uint32_t* sAl = sAh + AW;
        const uint32_t* sBh = sAl + AW;
        const uint32_t* sBl = sBh + BW;
        #pragma unroll
        for (int kc = 0; kc < 2; kc++) {
            uint32_t ah[MT][4], al[MT][4];
            #pragma unroll
            for (int mt = 0; mt < MT; mt++) {
                const int base = ((kc * M16 + wm * MT + mt) * 32 + lane) * 4;
                const uint4 vh = *(const uint4*)&sAh[base];
                ah[mt][0] = vh.x; ah[mt][1] = vh.y; ah[mt][2] = vh.z; ah[mt][3] = vh.w;
                const uint4 vl = *(const uint4*)&sAl[base];
                al[mt][0] = vl.x; al[mt][1] = vl.y; al[mt][2] = vl.z; al[mt][3] = vl.w;
            }
            #pragma unroll
            for (int j = 0; j < NT; j++) {
                const int base = ((kc * N8 + wn * NT + j) * 32 + lane) * 2;
                uint32_t bh[2], bl[2];
                const uint2 vh = *(const uint2*)&sBh[base]; bh[0] = vh.x; bh[1] = vh.y;
                const uint2 vl = *(const uint2*)&sBl[base]; bl[0] = vl.x; bl[1] = vl.y;
                #pragma unroll
                for (int mt = 0; mt < MT; mt++) {
                    mma_fp16(c[mt][j], ah[mt], bh);
                    mma_fp16(c[mt][j], al[mt], bh);
                    mma_fp16(c[mt][j], ah[mt], bl);
                }
            }
        }
    };

    cpA(0, 0); cpB(0, 0); CP_COMMIT();
    CP_WAIT0();
    __syncthreads();
    for (int ck = 0; ck < NC; ck++) {
        const int par = ck & 1;
        if (ck + 1 < NC) { cpA(ck + 1, par ^ 1); cpB(ck + 1, par ^ 1); CP_COMMIT(); }
        compute_chunk(par);
        CP_WAIT0();
        __syncthreads();
    }

    const int g = lane >> 2, t = lane & 3;
    #pragma unroll
    for (int mt = 0; mt < MT; mt++) {
        const int row0 = wm * MT * 16 + mt * 16 + g;
        #pragma unroll
        for (int j = 0; j < NT; j++) {
            const int col = wn * NT * 8 + j * 8 + t * 2;
            if constexpr (HALF_OUT) {
                // write as A-frag layout: lane==g*4+t owns exactly these slots
                const int m16g = m0 / 16 + wm * MT + mt;
                const int k16  = (n0 + wn * NT * 8 + j * 8) / 16;
                const int s0   = 2 * (j & 1);
                const size_t wadr = ((size_t)(k16 * OUT_R16 + m16g) * 32 + lane) * 4 + s0;
                uint2 val;
                val.x = pack_hi2(c[mt][j][0], c[mt][j][1]);   // rows row0,  cols col,col+1
                val.y = pack_hi2(c[mt][j][2], c[mt][j][3]);   // rows row0+8
                *(uint2*)&Cf[wadr] = val;
            } else {
                *(float2*)&C[(size_t)(m0 + row0) * DK + n0 + col] =
                    make_float2(c[mt][j][0], c[mt][j][1]);
                *(float2*)&C[(size_t)(m0 + row0 + 8) * DK + n0 + col] =
                    make_float2(c[mt][j][2], c[mt][j][3]);
            }
        }
    }
}

// k1: up[1024,256] = u @ Wu^T (fp32 out). 64x32 tiles, 128 thr, grid (8,16).
__global__ __launch_bounds__(128, 4) void k1_up() {
    gemm_core<64, 32, 2, 2, DL, 1024, DK, false, 0>(
        uA_h, uA_l, WuB_h, WuB_l, g_up, nullptr, blockIdx.y * 64, blockIdx.x * 32);
}

// k2: vp[4096,256] = v @ Wv^T, emitted as fp16 A-frags. 64x64, 128 thr, grid (4,64).
__global__ __launch_bounds__(128, 4) void k2_vp() {
    gemm_core<64, 64, 2, 2, DR, Bsz * Rr, DK, true, 256>(
        vA_h, vA_l, WvB_h, WvB_l, nullptr, vpA_h, blockIdx.y * 64, blockIdx.x * 64);
}

// ---- k3: out[bm] = relu( (vp_h[b] .* up_h[bm]) @ Wp_h^T + bp ), pure fp16 ----
// 128x256 tile, 16 warps (4x4), BK=64 (4 k16/chunk), all-cp.async double buffer.
constexpr int K3_AW = 4096;                 // A words per chunk (128 x 64 half)
constexpr int K3_BW = 8192;                 // B words per chunk (256 x 64 half)
constexpr int K3_STAGE = K3_AW + K3_BW;     // 12288 words
constexpr int K3_OFF = 384;                 // w2[128] + bias[256]
constexpr int SMEM_K3 = (K3_OFF + 2 * K3_STAGE) * 4;   // 99840 B

__global__ __launch_bounds__(512, 1) void k3_fuse(const float* __restrict__ bp,
                                                  float* __restrict__ out) {
    const int bm = blockIdx.x, b = bm >> 5;
    extern __shared__ uint32_t smem[];
    uint32_t* w2 = smem;                    // 128 half2 of up[bm]
    float* bs = (float*)(smem + 128);       // 256 bias
    const int tid = threadIdx.x;
    const int wid = tid >> 5, lane = tid & 31;
    const int wm = wid & 3, wn = wid >> 2;
    const int g = lane >> 2, t = lane & 3;

    if (tid < 128) {
        const float2 x = *(const float2*)&g_up[(size_t)bm * DK + tid * 2];
        w2[tid] = pack_hi2(x.x, x.y);
    }
    if (tid < 256) bs[tid] = bp[tid];

    float c[2][8][4] = {};

    auto cpA = [&](int ck, int st) {
        uint32_t* sA = smem + K3_OFF + st * K3_STAGE;
        #pragma unroll
        for (int j = 0; j < 2; j++) {
            const int w = (j * 512 + tid) * 4;
            const int lb = w >> 7, off = w & 127;
            const int kch = lb >> 3, m16l = lb & 7;
            const size_t gw = ((size_t)((ck * 4 + kch) * 256 + b * 8 + m16l)) * 128 + off;
            cp16(&sA[w], &vpA_h[gw]);
        }
    };
    auto cpB = [&](int ck, int st) {
        uint32_t* sB = smem + K3_OFF + st * K3_STAGE + K3_AW;
        #pragma unroll
        for (int j = 0; j < 4; j++) {
            const int w = (j * 512 + tid) * 4;
            const int lb = w >> 6, off = w & 63;
            const int kch = lb >> 5, n8 = lb & 31;
            const size_t gw = ((size_t)((ck * 4 + kch) * 32 + n8)) * 64 + off;
            cp16(&sB[w], &WpB_h[gw]);
        }
    };

    auto compute_chunk = [&](int ck, int st) {
        const uint32_t* sA = smem + K3_OFF + st * K3_STAGE;
        const uint32_t* sB = sA + K3_AW;
        #pragma unroll
        for (int kc = 0; kc < 4; kc++) {
            const uint32_t wlo = w2[(ck * 4 + kc) * 8 + t];
            const uint32_t whi = w2[(ck * 4 + kc) * 8 + 4 + t];
            uint32_t ah[2][4];
            #pragma unroll
            for (int mt = 0; mt < 2; mt++) {
                const int base = ((kc * 8 + wm * 2 + mt) * 32 + lane) * 4;
                const uint4 vh = *(const uint4*)&sA[base];
                ah[mt][0] = hmul2u(vh.x, wlo);
                ah[mt][1] = hmul2u(vh.y, wlo);
                ah[mt][2] = hmul2u(vh.z, whi);
                ah[mt][3] = hmul2u(vh.w, whi);
            }
            #pragma unroll
            for (int j = 0; j < 8; j++) {
                const int base = ((kc * 32 + wn * 8 + j) * 32 + lane) * 2;
                uint32_t bh[2];
                const uint2 vb = *(const uint2*)&sB[base];
                bh[0] = vb.x; bh[1] = vb.y;
                #pragma unroll
                for (int mt = 0; mt < 2; mt++)
                    mma_fp16(c[mt][j], ah[mt], bh);
            }
        }
    };

    cpA(0, 0); cpB(0, 0); CP_COMMIT();
    CP_WAIT0();
    __syncthreads();    // also covers w2/bs visibility
    #pragma unroll
    for (int ck = 0; ck < 4; ck++) {
        const int par = ck & 1;
        if (ck + 1 < 4) { cpA(ck + 1, par ^ 1); cpB(ck + 1, par ^ 1); CP_COMMIT(); }
        compute_chunk(ck, par);
        CP_WAIT0();
        __syncthreads();
    }

    float* __restrict__ O = out + (size_t)bm * Rr * DF;
    #pragma unroll
    for (int mt = 0; mt < 2; mt++) {
        const int row0 = wm * 32 + mt * 16 + g;
        #pragma unroll
        for (int j = 0; j < 8; j++) {
            const int col = wn * 64 + j * 8 + t * 2;
            const float b0 = bs[col], b1 = bs[col + 1];
            float2 v0, v1;
            v0.x = fmaxf(c[mt][j][0] + b0, 0.0f);
            v0.y = fmaxf(c[mt][j][1] + b1, 0.0f);
            v1.x = fmaxf(c[mt][j][2] + b0, 0.0f);
            v1.y = fmaxf(c[mt][j][3] + b1, 0.0f);
            *(float2*)&O[(size_t)row0 * DF + col]       = v0;
            *(float2*)&O[(size_t)(row0 + 8) * DF + col] = v1;
        }
    }
}

constexpr int SMEM_K1 = (2 * (2 * 64 * 16 + 2 * 32 * 16)) * 4;   // 24576
constexpr int SMEM_K2 = (2 * (2 * 64 * 16 + 2 * 64 * 16)) * 4;   // 32768

} // namespace

extern "C" void kernel_launch(void* const* d_in, const int* in_sizes, int n_in,
                              void* d_out, int out_size)
{
    (void)in_sizes; (void)n_in; (void)out_size;
    const float* u  = (const float*)d_in[0];   // (32, 32, 1024)
    const float* v  = (const float*)d_in[1];   // (32, 128, 2048)
    const float* Wu = (const float*)d_in[2];   // (256, 1024)
    const float* Wv = (const float*)d_in[3];   // (256, 2048)
    const float* Wp = (const float*)d_in[4];   // (256, 256)
    const float* bp = (const float*)d_in[5];   // (256,)
    float* out = (float*)d_out;                // (32, 32, 128, 256)

    cudaFuncSetAttribute(k1_up,   cudaFuncAttributeMaxDynamicSharedMemorySize, SMEM_K1);
    cudaFuncSetAttribute(k2_vp,   cudaFuncAttributeMaxDynamicSharedMemorySize, SMEM_K2);
    cudaFuncSetAttribute(k3_fuse, cudaFuncAttributeMaxDynamicSharedMemorySize, SMEM_K3);

    prep_u <<<(64 * 64 * 32)   / 256, 256>>>(u);
    prep_v <<<(256 * 128 * 32) / 256, 256>>>(v);
    prep_wu<<<(32 * 64 * 32)   / 256, 256>>>(Wu);
    prep_wv<<<(32 * 128 * 32)  / 256, 256>>>(Wv);
    prep_wp<<<(32 * 16 * 32)   / 256, 256>>>(Wp);

    k1_up<<<dim3(8, 16), 128, SMEM_K1>>>();           // 128 CTAs
    k2_vp<<<dim3(4, 64), 128, SMEM_K2>>>();           // 256 CTAs
    k3_fuse<<<1024, 512, SMEM_K3>>>(bp, out);         // 1024 CTAs
}

// round 13
// speedup vs baseline: 5.0953x; 1.0853x over previous
#include <cuda_runtime.h>
#include <cuda_fp16.h>
#include <cstdint>

// LowRankBilinearFusion, fp16 mma.sync.
//  k1 (up proj): 3-term fp16 split (near-fp32; up feeds the bilinear scale).
//  k2 (vp proj): 2-term Ah*Bh + Ah*Bl  (= fp16(v) @ Wv at ~fp32 weight precision;
//     vp is fp16-rounded on store anyway). Emits vp as pre-permuted fp16 A-frags.
//  k3: pure fp16, all-cp.async; A = hmul2(vp_h, up_h) scaled in registers.

namespace {

constexpr int Bsz = 32, Mq = 32, Rr = 128;
constexpr int DL = 1024, DR = 2048, DK = 256, DF = 256;

// ---- global scratch (device-code references only) ----
__device__ float g_up[Bsz * Mq * DK];                               // fp32 up
__device__ uint32_t vpA_h[(size_t)Bsz * Rr * DK / 2];               // vp as fp16 A-frags
__device__ uint32_t uA_h[DL * Bsz * Mq / 2],  uA_l[DL * Bsz * Mq / 2];
__device__ uint32_t vA_h[(size_t)Bsz * Rr * DR / 2];                // v hi only (2-term k2)
__device__ uint32_t WuB_h[DK * DL / 2], WuB_l[DK * DL / 2];
__device__ uint32_t WvB_h[DK * DR / 2], WvB_l[DK * DR / 2];
__device__ uint32_t WpB_h[DF * DK / 2];

__device__ __forceinline__ void mma_fp16(float* c, const uint32_t* a, const uint32_t* b) {
    asm volatile(
        "mma.sync.aligned.m16n8k16.row.col.f32.f16.f16.f32 "
        "{%0,%1,%2,%3}, {%4,%5,%6,%7}, {%8,%9}, {%0,%1,%2,%3};"
        : "+f"(c[0]), "+f"(c[1]), "+f"(c[2]), "+f"(c[3])
        : "r"(a[0]), "r"(a[1]), "r"(a[2]), "r"(a[3]), "r"(b[0]), "r"(b[1]));
}

__device__ __forceinline__ void split2(float x, __half& hi, __half& lo) {
    hi = __float2half_rn(x);
    lo = __float2half_rn(x - __half2float(hi));
}
__device__ __forceinline__ uint32_t pack2(__half a, __half b) {
    return (uint32_t)__half_as_ushort(a) | ((uint32_t)__half_as_ushort(b) << 16);
}
__device__ __forceinline__ void split_pack2(float x0, float x1, uint32_t& h, uint32_t& l) {
    __half h0, l0, h1, l1;
    split2(x0, h0, l0); split2(x1, h1, l1);
    h = pack2(h0, h1); l = pack2(l0, l1);
}
__device__ __forceinline__ uint32_t pack_hi2(float x0, float x1) {
    return pack2(__float2half_rn(x0), __float2half_rn(x1));
}
__device__ __forceinline__ uint32_t hmul2u(uint32_t a, uint32_t b) {
    __half2 r = __hmul2(*(__half2*)&a, *(__half2*)&b);
    return *(uint32_t*)&r;
}

__device__ __forceinline__ void cp16(void* sdst, const void* gsrc) {
    uint32_t sa = (uint32_t)__cvta_generic_to_shared(sdst);
    asm volatile("cp.async.cg.shared.global [%0], [%1], 16;" :: "r"(sa), "l"(gsrc) : "memory");
}
#define CP_COMMIT() asm volatile("cp.async.commit_group;" ::: "memory")
#define CP_WAIT0()  asm volatile("cp.async.wait_group 0;"  ::: "memory")

// ---- prep: fp32 row-major -> permuted fp16 frag buffers ----
template <bool WRITE_LO>
__device__ __forceinline__ void prep_A_body(
    const float* __restrict__ X, uint32_t* __restrict__ H,
    uint32_t* __restrict__ L, int ROWS16, int K)
{
    const int t = blockIdx.x * blockDim.x + threadIdx.x;
    const int lane = t & 31, fb = t >> 5;
    const int m16 = fb % ROWS16, k16 = fb / ROWS16;
    const int g = lane >> 2, tt = lane & 3;
    uint32_t h[4], l[4];
    #pragma unroll
    for (int s = 0; s < 4; s++) {
        const int row = m16 * 16 + (s & 1) * 8 + g;
        const int kk  = k16 * 16 + (s >> 1) * 8 + 2 * tt;
        const float2 x = *(const float2*)&X[(size_t)row * K + kk];
        if (WRITE_LO) split_pack2(x.x, x.y, h[s], l[s]);
        else          h[s] = pack_hi2(x.x, x.y);
    }
    const size_t o = (size_t)(fb * 32 + lane) * 4;
    *(uint4*)&H[o] = make_uint4(h[0], h[1], h[2], h[3]);
    if (WRITE_LO) *(uint4*)&L[o] = make_uint4(l[0], l[1], l[2], l[3]);
}

__device__ __forceinline__ void prep_B_body(
    const float* __restrict__ X, uint32_t* __restrict__ H,
    uint32_t* __restrict__ L, int NROWS8, int K, bool write_lo)
{
    const int t = blockIdx.x * blockDim.x + threadIdx.x;
    const int lane = t & 31, fb = t >> 5;
    const int n8 = fb % NROWS8, k16 = fb / NROWS8;
    const int g = lane >> 2, tt = lane & 3;
    uint32_t h[2], l[2];
    #pragma unroll
    for (int s = 0; s < 2; s++) {
        const int row = n8 * 8 + g;
        const int kk  = k16 * 16 + s * 8 + 2 * tt;
        const float2 x = *(const float2*)&X[(size_t)row * K + kk];
        split_pack2(x.x, x.y, h[s], l[s]);
    }
    const size_t o = (size_t)(fb * 32 + lane) * 2;
    *(uint2*)&H[o] = make_uint2(h[0], h[1]);
    if (write_lo) *(uint2*)&L[o] = make_uint2(l[0], l[1]);
}

__global__ void prep_u (const float* __restrict__ X) { prep_A_body<true >(X, uA_h, uA_l, 64,  DL); }
__global__ void prep_v (const float* __restrict__ X) { prep_A_body<false>(X, vA_h, nullptr, 256, DR); }
__global__ void prep_wu(const float* __restrict__ X) { prep_B_body(X, WuB_h, WuB_l, 32, DL, true); }
__global__ void prep_wv(const float* __restrict__ X) { prep_B_body(X, WvB_h, WvB_l, 32, DR, true); }
__global__ void prep_wp(const float* __restrict__ X) { prep_B_body(X, WpB_h, nullptr, 32, DK, false); }

// ---- GEMM core for k1/k2 (A from pre-permuted frags) ----
// A_LO / B_LO: include the corresponding lo-split terms (and stage lo buffers).
// HALF_OUT: write C as pre-permuted fp16 A-frag buffer (OUT_R16 = out rows/16).
template <int TM, int TN, int WM, int WN, int KDIM, int AROWS, int NROWS,
          bool A_LO, bool B_LO, bool HALF_OUT, int OUT_R16>
__device__ __forceinline__ void gemm_core(
    const uint32_t* __restrict__ Agh, const uint32_t* __restrict__ Agl,
    const uint32_t* __restrict__ Bgh, const uint32_t* __restrict__ Bgl,
    float* __restrict__ C, uint32_t* __restrict__ Cf, int m0, int n0)
{
    constexpr int THREADS = WM * WN * 32;
    constexpr int MT = TM / WM / 16;
    constexpr int NT = TN / WN / 8;
    constexpr int NC = KDIM / 32;
    constexpr int AW = TM * 16;
    constexpr int BW = TN * 16;
    constexpr int M16 = TM / 16, N8 = TN / 8;
    constexpr int NA = A_LO ? 2 : 1;
    constexpr int NB = B_LO ? 2 : 1;

    extern __shared__ uint32_t smem[];
    constexpr int STAGE = NA * AW + NB * BW;

    const int tid = threadIdx.x;
    const int wid = tid >> 5, lane = tid & 31;
    const int wm = wid % WM, wn = wid / WM;

    float c[MT][NT][4] = {};

    auto cpA = [&](int ck, int st) {
        uint32_t* sAh = smem + st * STAGE;
        uint32_t* sAl = sAh + AW;
        constexpr int AU4 = AW / (4 * THREADS);
        #pragma unroll
        for (int j = 0; j < AU4; j++) {
            const int w = (j * THREADS + tid) * 4;
            const int lb = w >> 7, off = w & 127;
            const int k16h = lb / M16, m16l = lb % M16;
            const size_t gw = ((size_t)(2 * ck + k16h) * (AROWS / 16) + m0 / 16 + m16l) * 128 + off;
            cp16(&sAh[w], &Agh[gw]);
            if (A_LO) cp16(&sAl[w], &Agl[gw]);
        }
    };
    auto cpB = [&](int ck, int st) {
        uint32_t* sBh = smem + st * STAGE + NA * AW;
        uint32_t* sBl = sBh + BW;
        constexpr int BU4 = BW / (4 * THREADS);
        #pragma unroll
        for (int j = 0; j < BU4; j++) {
            const int w = (j * THREADS + tid) * 4;
            const int lb = w >> 6, off = w & 63;
            const int k16h = lb / N8, n8l = lb % N8;
            const size_t gw = ((size_t)(2 * ck + k16h) * (NROWS / 8) + n0 / 8 + n8l) * 64 + off;
            cp16(&sBh[w], &Bgh[gw]);
            if (B_LO) cp16(&sBl[w], &Bgl[gw]);
        }
    };

    auto compute_chunk = [&](int st) {
        const uint32_t* sAh = smem + st * STAGE;
        const uint32_t* sAl = sAh + AW;
        const uint32_t* sBh = smem + st * STAGE + NA * AW;
        const uint32_t* sBl = sBh + BW;
        #pragma unroll
        for (int kc = 0; kc < 2; kc++) {
            uint32_t ah[MT][4], al[MT][4];
            #pragma unroll
            for (int mt = 0; mt < MT; mt++) {
                const int base = ((kc * M16 + wm * MT + mt) * 32 + lane) * 4;
                const uint4 vh = *(const uint4*)&sAh[base];
                ah[mt][0] = vh.x; ah[mt][1] = vh.y; ah[mt][2] = vh.z; ah[mt][3] = vh.w;
                if (A_LO) {
                    const uint4 vl = *(const uint4*)&sAl[base];
                    al[mt][0] = vl.x; al[mt][1] = vl.y; al[mt][2] = vl.z; al[mt][3] = vl.w;
                }
            }
            #pragma unroll
            for (int j = 0; j < NT; j++) {
                const int base = ((kc * N8 + wn * NT + j) * 32 + lane) * 2;
                uint32_t bh[2], bl[2];
                const uint2 vh = *(const uint2*)&sBh[base]; bh[0] = vh.x; bh[1] = vh.y;
                if (B_LO) { const uint2 vl = *(const uint2*)&sBl[base]; bl[0] = vl.x; bl[1] = vl.y; }
                #pragma unroll
                for (int mt = 0; mt < MT; mt++) {
                    mma_fp16(c[mt][j], ah[mt], bh);
                    if (A_LO) mma_fp16(c[mt][j], al[mt], bh);
                    if (B_LO) mma_fp16(c[mt][j], ah[mt], bl);
                }
            }
        }
    };

    cpA(0, 0); cpB(0, 0); CP_COMMIT();
    CP_WAIT0();
    __syncthreads();
    for (int ck = 0; ck < NC; ck++) {
        const int par = ck & 1;
        if (ck + 1 < NC) { cpA(ck + 1, par ^ 1); cpB(ck + 1, par ^ 1); CP_COMMIT(); }
        compute_chunk(par);
        CP_WAIT0();
        __syncthreads();
    }

    const int g = lane >> 2, t = lane & 3;
    #pragma unroll
    for (int mt = 0; mt < MT; mt++) {
        const int row0 = wm * MT * 16 + mt * 16 + g;
        #pragma unroll
        for (int j = 0; j < NT; j++) {
            const int col = wn * NT * 8 + j * 8 + t * 2;
            if constexpr (HALF_OUT) {
                const int m16g = m0 / 16 + wm * MT + mt;
                const int k16  = (n0 + wn * NT * 8 + j * 8) / 16;
                const int s0   = 2 * (j & 1);
                const size_t wadr = ((size_t)(k16 * OUT_R16 + m16g) * 32 + lane) * 4 + s0;
                uint2 val;
                val.x = pack_hi2(c[mt][j][0], c[mt][j][1]);
                val.y = pack_hi2(c[mt][j][2], c[mt][j][3]);
                *(uint2*)&Cf[wadr] = val;
            } else {
                *(float2*)&C[(size_t)(m0 + row0) * DK + n0 + col] =
                    make_float2(c[mt][j][0], c[mt][j][1]);
                *(float2*)&C[(size_t)(m0 + row0 + 8) * DK + n0 + col] =
                    make_float2(c[mt][j][2], c[mt][j][3]);
            }
        }
    }
}

// k1: up[1024,256] = u @ Wu^T (fp32 out), 3-term. 64x32 tiles, grid (8,16).
__global__ __launch_bounds__(128, 4) void k1_up() {
    gemm_core<64, 32, 2, 2, DL, 1024, DK, true, true, false, 0>(
        uA_h, uA_l, WuB_h, WuB_l, g_up, nullptr, blockIdx.y * 64, blockIdx.x * 32);
}

// k2: vp = fp16(v) @ Wv^T (2-term: Ah*Bh + Ah*Bl), fp16-frag out. grid (4,64).
__global__ __launch_bounds__(128, 4) void k2_vp() {
    gemm_core<64, 64, 2, 2, DR, Bsz * Rr, DK, false, true, true, 256>(
        vA_h, nullptr, WvB_h, WvB_l, nullptr, vpA_h, blockIdx.y * 64, blockIdx.x * 64);
}

// ---- k3: out[bm] = relu( (vp_h[b] .* up_h[bm]) @ Wp_h^T + bp ), pure fp16 ----
constexpr int K3_AW = 4096;                 // A words per chunk (128 x 64 half)
constexpr int K3_BW = 8192;                 // B words per chunk (256 x 64 half)
constexpr int K3_STAGE = K3_AW + K3_BW;
constexpr int K3_OFF = 384;
constexpr int SMEM_K3 = (K3_OFF + 2 * K3_STAGE) * 4;   // 99840 B

__global__ __launch_bounds__(512, 1) void k3_fuse(const float* __restrict__ bp,
                                                  float* __restrict__ out) {
    const int bm = blockIdx.x, b = bm >> 5;
    extern __shared__ uint32_t smem[];
    uint32_t* w2 = smem;
    float* bs = (float*)(smem + 128);
    const int tid = threadIdx.x;
    const int wid = tid >> 5, lane = tid & 31;
    const int wm = wid & 3, wn = wid >> 2;
    const int g = lane >> 2, t = lane & 3;

    if (tid < 128) {
        const float2 x = *(const float2*)&g_up[(size_t)bm * DK + tid * 2];
        w2[tid] = pack_hi2(x.x, x.y);
    }
    if (tid < 256) bs[tid] = bp[tid];

    float c[2][8][4] = {};

    auto cpA = [&](int ck, int st) {
        uint32_t* sA = smem + K3_OFF + st * K3_STAGE;
        #pragma unroll
        for (int j = 0; j < 2; j++) {
            const int w = (j * 512 + tid) * 4;
            const int lb = w >> 7, off = w & 127;
            const int kch = lb >> 3, m16l = lb & 7;
            const size_t gw = ((size_t)((ck * 4 + kch) * 256 + b * 8 + m16l)) * 128 + off;
            cp16(&sA[w], &vpA_h[gw]);
        }
    };
    auto cpB = [&](int ck, int st) {
        uint32_t* sB = smem + K3_OFF + st * K3_STAGE + K3_AW;
        #pragma unroll
        for (int j = 0; j < 4; j++) {
            const int w = (j * 512 + tid) * 4;
            const int lb = w >> 6, off = w & 63;
            const int kch = lb >> 5, n8 = lb & 31;
            const size_t gw = ((size_t)((ck * 4 + kch) * 32 + n8)) * 64 + off;
            cp16(&sB[w], &WpB_h[gw]);
        }
    };

    auto compute_chunk = [&](int ck, int st) {
        const uint32_t* sA = smem + K3_OFF + st * K3_STAGE;
        const uint32_t* sB = sA + K3_AW;
        #pragma unroll
        for (int kc = 0; kc < 4; kc++) {
            const uint32_t wlo = w2[(ck * 4 + kc) * 8 + t];
            const uint32_t whi = w2[(ck * 4 + kc) * 8 + 4 + t];
            uint32_t ah[2][4];
            #pragma unroll
            for (int mt = 0; mt < 2; mt++) {
                const int base = ((kc * 8 + wm * 2 + mt) * 32 + lane) * 4;
                const uint4 vh = *(const uint4*)&sA[base];
                ah[mt][0] = hmul2u(vh.x, wlo);
                ah[mt][1] = hmul2u(vh.y, wlo);
                ah[mt][2] = hmul2u(vh.z, whi);
                ah[mt][3] = hmul2u(vh.w, whi);
            }
            #pragma unroll
            for (int j = 0; j < 8; j++) {
                const int base = ((kc * 32 + wn * 8 + j) * 32 + lane) * 2;
                uint32_t bh[2];
                const uint2 vb = *(const uint2*)&sB[base];
                bh[0] = vb.x; bh[1] = vb.y;
                #pragma unroll
                for (int mt = 0; mt < 2; mt++)
                    mma_fp16(c[mt][j], ah[mt], bh);
            }
        }
    };

    cpA(0, 0); cpB(0, 0); CP_COMMIT();
    CP_WAIT0();
    __syncthreads();
    #pragma unroll
    for (int ck = 0; ck < 4; ck++) {
        const int par = ck & 1;
        if (ck + 1 < 4) { cpA(ck + 1, par ^ 1); cpB(ck + 1, par ^ 1); CP_COMMIT(); }
        compute_chunk(ck, par);
        CP_WAIT0();
        __syncthreads();
    }

    float* __restrict__ O = out + (size_t)bm * Rr * DF;
    #pragma unroll
    for (int mt = 0; mt < 2; mt++) {
        const int row0 = wm * 32 + mt * 16 + g;
        #pragma unroll
        for (int j = 0; j < 8; j++) {
            const int col = wn * 64 + j * 8 + t * 2;
            const float b0 = bs[col], b1 = bs[col + 1];
            float2 v0, v1;
            v0.x = fmaxf(c[mt][j][0] + b0, 0.0f);
            v0.y = fmaxf(c[mt][j][1] + b1, 0.0f);
            v1.x = fmaxf(c[mt][j][2] + b0, 0.0f);
            v1.y = fmaxf(c[mt][j][3] + b1, 0.0f);
            *(float2*)&O[(size_t)row0 * DF + col]       = v0;
            *(float2*)&O[(size_t)(row0 + 8) * DF + col] = v1;
        }
    }
}

constexpr int SMEM_K1 = (2 * (2 * 64 * 16 + 2 * 32 * 16)) * 4;   // 24576
constexpr int SMEM_K2 = (2 * (1 * 64 * 16 + 2 * 64 * 16)) * 4;   // 24576

} // namespace

extern "C" void kernel_launch(void* const* d_in, const int* in_sizes, int n_in,
                              void* d_out, int out_size)
{
    (void)in_sizes; (void)n_in; (void)out_size;
    const float* u  = (const float*)d_in[0];   // (32, 32, 1024)
    const float* v  = (const float*)d_in[1];   // (32, 128, 2048)
    const float* Wu = (const float*)d_in[2];   // (256, 1024)
    const float* Wv = (const float*)d_in[3];   // (256, 2048)
    const float* Wp = (const float*)d_in[4];   // (256, 256)
    const float* bp = (const float*)d_in[5];   // (256,)
    float* out = (float*)d_out;                // (32, 32, 128, 256)

    cudaFuncSetAttribute(k1_up,   cudaFuncAttributeMaxDynamicSharedMemorySize, SMEM_K1);
    cudaFuncSetAttribute(k2_vp,   cudaFuncAttributeMaxDynamicSharedMemorySize, SMEM_K2);
    cudaFuncSetAttribute(k3_fuse, cudaFuncAttributeMaxDynamicSharedMemorySize, SMEM_K3);

    prep_u <<<(64 * 64 * 32)   / 256, 256>>>(u);
    prep_v <<<(256 * 128 * 32) / 256, 256>>>(v);
    prep_wu<<<(32 * 64 * 32)   / 256, 256>>>(Wu);
    prep_wv<<<(32 * 128 * 32)  / 256, 256>>>(Wv);
    prep_wp<<<(32 * 16 * 32)   / 256, 256>>>(Wp);

    k1_up<<<dim3(8, 16), 128, SMEM_K1>>>();           // 128 CTAs
    k2_vp<<<dim3(4, 64), 128, SMEM_K2>>>();           // 256 CTAs
    k3_fuse<<<1024, 512, SMEM_K3>>>(bp, out);         // 1024 CTAs
}